// round 12
// baseline (speedup 1.0000x reference)
#include <cuda_runtime.h>
#include <cuda_fp16.h>
#include <cstdint>

#define CDIV(a,b) (((a)+(b)-1)/(b))

// ---------------- static device scratch ----------------
__device__ __align__(16) half  g_WtpT  [512 * 1024];
__device__ __align__(16) half  g_W2T   [512 * 64];
__device__ __align__(16) half  g_linWT [128 * 512];
__device__ __align__(16) float g_hidden[160000 * 64];
__device__ __align__(16) half  g_radial[160000 * 512];
__device__ __align__(16) half  g_value [160000 * 512];
__device__ __align__(16) float g_alpha [250000 * 8];
__device__              int    g_seg   [160001];
__device__ __align__(16) half  g_fea   [160000 * 512];

// ---------------- PTX helpers ----------------
__device__ __forceinline__ void mma_f16(float* c, const uint32_t* a, const uint32_t* b) {
    asm volatile(
        "mma.sync.aligned.m16n8k16.row.col.f32.f16.f16.f32 "
        "{%0,%1,%2,%3},{%4,%5,%6,%7},{%8,%9},{%0,%1,%2,%3};\n"
        : "+f"(c[0]), "+f"(c[1]), "+f"(c[2]), "+f"(c[3])
        : "r"(a[0]), "r"(a[1]), "r"(a[2]), "r"(a[3]), "r"(b[0]), "r"(b[1]));
}

__device__ __forceinline__ void ldsm4(uint32_t* d, const half* p) {
    uint32_t a = (uint32_t)__cvta_generic_to_shared(p);
    asm volatile("ldmatrix.sync.aligned.m8n8.x4.shared.b16 {%0,%1,%2,%3},[%4];\n"
        : "=r"(d[0]), "=r"(d[1]), "=r"(d[2]), "=r"(d[3]) : "r"(a));
}

__device__ __forceinline__ void cp16(void* smem, const void* gmem) {
    uint32_t s = (uint32_t)__cvta_generic_to_shared(smem);
    asm volatile("cp.async.cg.shared.global [%0], [%1], 16;\n" :: "r"(s), "l"(gmem));
}
#define CP_COMMIT() asm volatile("cp.async.commit_group;\n")
#define CP_WAIT0()  asm volatile("cp.async.wait_group 0;\n")
#define CP_WAIT1()  asm volatile("cp.async.wait_group 1;\n")

__device__ __forceinline__ uint32_t packh2(float a, float b) {
    half2 h = __floats2half2_rn(a, b);
    return *(uint32_t*)&h;
}

// f32x2 packed math (PTX-only; doubles fp32 FMA throughput, identical rounding)
__device__ __forceinline__ void fma2(unsigned long long& d, unsigned long long a,
                                     unsigned long long b) {
    asm("fma.rn.f32x2 %0, %1, %2, %0;" : "+l"(d) : "l"(a), "l"(b));
}
__device__ __forceinline__ unsigned long long pk2(float x, float y) {
    unsigned long long r;
    asm("mov.b64 %0, {%1, %2};" : "=l"(r) : "f"(x), "f"(y));
    return r;
}
__device__ __forceinline__ float2 up2(unsigned long long v) {
    float2 f;
    asm("mov.b64 {%0, %1}, %2;" : "=f"(f.x), "=f"(f.y) : "l"(v));
    return f;
}

// one 64-deep K-chunk of mma on 128x128 tile; warp covers 32(m)x64(n).
// smem row stride = 72 halfs (144B): ldmatrix row addrs hit 32 distinct banks.
__device__ __forceinline__ void tile_mma(const half* sA, const half* sB,
                                         int wm, int wn, int lane,
                                         float acc[2][8][4]) {
    int r15 = lane & 15;
    int a_k8 = ((lane >> 4) & 1) * 8;
    int b_r8 = ((lane >> 4) & 1) * 8;
    int b_k8 = lane & 8;
    int l7 = lane & 7;
#pragma unroll
    for (int ks = 0; ks < 4; ks++) {
        uint32_t af[2][4];
#pragma unroll
        for (int mt = 0; mt < 2; mt++)
            ldsm4(af[mt], sA + (wm + mt * 16 + r15) * 72 + ks * 16 + a_k8);
        uint32_t bf[4][4];
#pragma unroll
        for (int np = 0; np < 4; np++)
            ldsm4(bf[np], sB + (wn + np * 16 + b_r8 + l7) * 72 + ks * 16 + b_k8);
#pragma unroll
        for (int np = 0; np < 4; np++) {
            mma_f16(acc[0][2 * np],     af[0], &bf[np][0]);
            mma_f16(acc[0][2 * np + 1], af[0], &bf[np][2]);
            mma_f16(acc[1][2 * np],     af[1], &bf[np][0]);
            mma_f16(acc[1][2 * np + 1], af[1], &bf[np][2]);
        }
    }
}

// ---------------- weight prep ----------------
__global__ void k_prep(const float* __restrict__ Wtp, const float* __restrict__ W2,
                       const float* __restrict__ linW) {
    int i = blockIdx.x * blockDim.x + threadIdx.x;
    int stride = gridDim.x * blockDim.x;
    for (int idx = i; idx < 512 * 1024; idx += stride) {
        int n = idx >> 10, k = idx & 1023;
        g_WtpT[idx] = __float2half_rn(Wtp[k * 512 + n]);
    }
    for (int idx = i; idx < 512 * 64; idx += stride) {
        int n = idx >> 6, k = idx & 63;
        g_W2T[idx] = __float2half_rn(W2[k * 512 + n]);
    }
    for (int idx = i; idx < 128 * 512; idx += stride) {
        int n = idx >> 9, k = idx & 511;
        g_linWT[idx] = __float2half_rn(linW[k * 128 + n]);
    }
}

// ---------------- hidden = silu(emb @ W1 + b1) ----------------
__global__ void k_hidden(const float* __restrict__ emb, const float* __restrict__ W1,
                         const float* __restrict__ b1, int E) {
    __shared__ float s_e[4][64];
    int tid = threadIdx.x;
    int slot = tid >> 6, j = tid & 63;
    int e = blockIdx.x * 4 + slot;
    int ec = min(e, E - 1);
    s_e[slot][j] = emb[ec * 64 + j];
    __syncthreads();
    float acc = b1[j];
#pragma unroll 8
    for (int i = 0; i < 64; i++) acc = fmaf(s_e[slot][i], W1[i * 64 + j], acc);
    float y = acc / (1.f + __expf(-acc));
    if (e < E) g_hidden[e * 64 + j] = y;
}

// ---------------- radial = hidden @ W2 + b2  (K=64 mma) ----------------
__global__ __launch_bounds__(256) void k_radial(const float* __restrict__ b2, int M) {
    __shared__ half sA[128 * 72];
    __shared__ half sB[128 * 72];
    int m0 = blockIdx.x * 128, n0 = blockIdx.y * 128;
    int tid = threadIdx.x, lane = tid & 31, wid = tid >> 5;
    int wm = (wid & 3) * 32, wn = (wid >> 2) * 64;
    int g = lane >> 2, tg = lane & 3;
    int row = tid >> 1, koff = (tid & 1) * 32;
    int erow = min(m0 + row, M - 1);

    float acc[2][8][4];
#pragma unroll
    for (int a = 0; a < 2; a++)
#pragma unroll
        for (int b = 0; b < 8; b++)
#pragma unroll
            for (int c = 0; c < 4; c++) acc[a][b][c] = 0.f;

    const float4* hp = (const float4*)(g_hidden + erow * 64 + koff);
#pragma unroll
    for (int j = 0; j < 8; j++) {
        float4 v = hp[j];
        *(half2*)&sA[row * 72 + koff + j * 4]     = __floats2half2_rn(v.x, v.y);
        *(half2*)&sA[row * 72 + koff + j * 4 + 2] = __floats2half2_rn(v.z, v.w);
    }
    {
        const uint4* s = (const uint4*)(g_W2T + (n0 + row) * 64 + koff);
        uint4* d = (uint4*)&sB[row * 72 + koff];
        d[0] = s[0]; d[1] = s[1]; d[2] = s[2]; d[3] = s[3];
    }
    __syncthreads();
    tile_mma(sA, sB, wm, wn, lane, acc);

#pragma unroll
    for (int mt = 0; mt < 2; mt++)
#pragma unroll
        for (int nt = 0; nt < 8; nt++) {
            int er = m0 + wm + mt * 16 + g;
            int cn = n0 + wn + nt * 8 + tg * 2;
            float bb0 = b2[cn], bb1 = b2[cn + 1];
            if (er < M)
                *(half2*)&g_radial[er * 512 + cn] =
                    __floats2half2_rn(acc[mt][nt][0] + bb0, acc[mt][nt][1] + bb1);
            if (er + 8 < M)
                *(half2*)&g_radial[(er + 8) * 512 + cn] =
                    __floats2half2_rn(acc[mt][nt][2] + bb0, acc[mt][nt][3] + bb1);
        }
}

// ---------------- value = (z @ W_tp) * radial ----------------
// K=1024, register-built A, 3-stage cp.async ring (B tile + ein slice per stage)
__global__ __launch_bounds__(256, 2) void k_value(const float* __restrict__ ein,
                                                  const float* __restrict__ esh, int M) {
    __shared__ half  sB[3][128 * 72];
    __shared__ float sE[3][128 * 4];
    int m0 = blockIdx.x * 128, n0 = blockIdx.y * 128;
    int tid = threadIdx.x, lane = tid & 31, wid = tid >> 5;
    int wm = (wid & 3) * 32, wn = (wid >> 2) * 64;
    int g = lane >> 2, tg = lane & 3;
    int row = tid >> 1, koff = (tid & 1) * 32;

    int b_r8 = ((lane >> 4) & 1) * 8;
    int b_k8 = lane & 8;
    int l7 = lane & 7;

    // local + clamped-global A-fragment rows (2 m-tiles x 2 row-halves)
    int lr[4], r[4];
#pragma unroll
    for (int q = 0; q < 4; q++) {
        lr[q] = wm + g + ((q & 1) ? 8 : 0) + ((q >> 1) ? 16 : 0);
        r[q]  = min(m0 + lr[q], M - 1);
    }

    // SH columns owned by this thread (fixed across all K)
    float shf[4][4];
#pragma unroll
    for (int q = 0; q < 4; q++) {
        const float* sp = esh + r[q] * 16;
        shf[q][0] = __ldg(&sp[tg * 2]);
        shf[q][1] = __ldg(&sp[tg * 2 + 1]);
        shf[q][2] = __ldg(&sp[tg * 2 + 8]);
        shf[q][3] = __ldg(&sp[tg * 2 + 9]);
    }

    // stage loaders
    int e_row = min(m0 + (tid & 127), M - 1);   // threads 0..127 load ein rows
    auto load_stage = [&](int s, int kc) {
        const half* src = g_WtpT + (n0 + row) * 1024 + kc * 64 + koff;
        half* dst = &sB[s][row * 72 + koff];
#pragma unroll
        for (int j = 0; j < 4; j++) cp16(dst + j * 8, src + j * 8);
        if (tid < 128)
            cp16(&sE[s][tid * 4], ein + e_row * 64 + kc * 4);
    };

    float acc[2][8][4];
#pragma unroll
    for (int a = 0; a < 2; a++)
#pragma unroll
        for (int b = 0; b < 8; b++)
#pragma unroll
            for (int c = 0; c < 4; c++) acc[a][b][c] = 0.f;

    // prologue: stage chunks 0 and 1
    load_stage(0, 0); CP_COMMIT();
    load_stage(1, 1); CP_COMMIT();
    CP_WAIT1();               // stage 0 complete
    __syncthreads();

    for (int kc = 0; kc < 16; kc++) {
        int p = kc % 3;
        if (kc < 14) { load_stage((kc + 2) % 3, kc + 2); CP_COMMIT(); }

        // ein values for this chunk from smem (broadcast LDS.128)
        float4 ev[4];
#pragma unroll
        for (int q = 0; q < 4; q++)
            ev[q] = *(const float4*)&sE[p][lr[q] * 4];

        const half* sBp = sB[p];
#pragma unroll
        for (int ks = 0; ks < 4; ks++) {
            float e0 = ((const float*)&ev[0])[ks];
            float e1 = ((const float*)&ev[1])[ks];
            float e2 = ((const float*)&ev[2])[ks];
            float e3 = ((const float*)&ev[3])[ks];
            uint32_t af[2][4];
            af[0][0] = packh2(e0 * shf[0][0], e0 * shf[0][1]);
            af[0][1] = packh2(e1 * shf[1][0], e1 * shf[1][1]);
            af[0][2] = packh2(e0 * shf[0][2], e0 * shf[0][3]);
            af[0][3] = packh2(e1 * shf[1][2], e1 * shf[1][3]);
            af[1][0] = packh2(e2 * shf[2][0], e2 * shf[2][1]);
            af[1][1] = packh2(e3 * shf[3][0], e3 * shf[3][1]);
            af[1][2] = packh2(e2 * shf[2][2], e2 * shf[2][3]);
            af[1][3] = packh2(e3 * shf[3][2], e3 * shf[3][3]);

            uint32_t bf[4][4];
#pragma unroll
            for (int np = 0; np < 4; np++)
                ldsm4(bf[np], sBp + (wn + np * 16 + b_r8 + l7) * 72 + ks * 16 + b_k8);
#pragma unroll
            for (int np = 0; np < 4; np++) {
                mma_f16(acc[0][2 * np],     af[0], &bf[np][0]);
                mma_f16(acc[0][2 * np + 1], af[0], &bf[np][2]);
                mma_f16(acc[1][2 * np],     af[1], &bf[np][0]);
                mma_f16(acc[1][2 * np + 1], af[1], &bf[np][2]);
            }
        }
        if (kc < 15) {
            CP_WAIT1();       // next stage complete (lookahead stage may still fly)
            __syncthreads();
        }
    }

    // epilogue: value = acc * radial (radial fp16, incl. bias)
#pragma unroll
    for (int mt = 0; mt < 2; mt++)
#pragma unroll
        for (int nt = 0; nt < 8; nt++) {
            int er = m0 + wm + mt * 16 + g;
            int cn = n0 + wn + nt * 8 + tg * 2;
            if (er < M) {
                float2 rr = __half22float2(*(const half2*)&g_radial[er * 512 + cn]);
                *(half2*)&g_value[er * 512 + cn] =
                    __floats2half2_rn(acc[mt][nt][0] * rr.x, acc[mt][nt][1] * rr.y);
            }
            if (er + 8 < M) {
                float2 rr = __half22float2(*(const half2*)&g_radial[(er + 8) * 512 + cn]);
                *(half2*)&g_value[(er + 8) * 512 + cn] =
                    __floats2half2_rn(acc[mt][nt][2] * rr.x, acc[mt][nt][3] * rr.y);
            }
        }
}

// ---------------- segment offsets (triple_idx0 sorted) ----------------
__global__ void k_seg(const int* __restrict__ t0, int E, int T) {
    int e = blockIdx.x * blockDim.x + threadIdx.x;
    if (e > E) return;
    int lo = 0, hi = T;
    while (lo < hi) {
        int mid = (lo + hi) >> 1;
        if (t0[mid] < e) lo = mid + 1; else hi = mid;
    }
    g_seg[e] = lo;
}

// ---------------- alpha MLPs (fp32, f32x2 packed FMA) ----------------
__global__ __launch_bounds__(128) void k_alpha(
    const float* __restrict__ emb2, const float* __restrict__ emb3,
    const float* __restrict__ aW1, const float* __restrict__ ab1,
    const float* __restrict__ ag1, const float* __restrict__ abe1,
    const float* __restrict__ aW2, const float* __restrict__ ab2,
    const float* __restrict__ ag2, const float* __restrict__ abe2,
    const float* __restrict__ aW3, const float* __restrict__ ab3, int T) {
    __shared__ __align__(16) float sW[64 * 64];
    __shared__ __align__(16) float sW3[64 * 8];
    __shared__ __align__(16) float sP[6 * 64];
    __shared__ __align__(16) float sb3[8];
    __shared__ float sx[64 * 129];
    int tid = threadIdx.x;
    int base = blockIdx.x * 128;
    int tri = base + tid;
    bool act = tri < T;
    float res[8];

    for (int br = 0; br < 2; br++) {
        const float* emb = br ? emb3 : emb2;
        __syncthreads();
        for (int li = tid; li < 128 * 64; li += 128) {
            int r = li >> 6, c = li & 63;
            int tt = min(base + r, T - 1);
            sx[c * 129 + r] = emb[tt * 64 + c];
        }
        for (int li = tid; li < 4096; li += 128) sW[li] = aW1[br * 4096 + li];
        for (int li = tid; li < 512; li += 128) sW3[li] = aW3[br * 512 + li];
        if (tid < 64) {
            sP[tid] = ab1[br * 64 + tid];        sP[64 + tid] = ag1[br * 64 + tid];
            sP[128 + tid] = abe1[br * 64 + tid]; sP[192 + tid] = ab2[br * 64 + tid];
            sP[256 + tid] = ag2[br * 64 + tid];  sP[320 + tid] = abe2[br * 64 + tid];
        }
        if (tid < 8) sb3[tid] = ab3[br * 8 + tid];
        __syncthreads();

        unsigned long long h2[32];
        // layer 1
#pragma unroll
        for (int j = 0; j < 32; j++) h2[j] = pk2(sP[2 * j], sP[2 * j + 1]);
        for (int i = 0; i < 64; i++) {
            float xv = sx[i * 129 + tid];
            unsigned long long xv2 = pk2(xv, xv);
            const ulonglong2* wr = (const ulonglong2*)(sW + i * 64);
#pragma unroll
            for (int j = 0; j < 16; j++) {
                ulonglong2 q = wr[j];
                fma2(h2[2 * j], xv2, q.x);
                fma2(h2[2 * j + 1], xv2, q.y);
            }
        }
        {
            float mu = 0.f;
#pragma unroll
            for (int j = 0; j < 32; j++) { float2 f = up2(h2[j]); mu += f.x + f.y; }
            mu *= (1.f / 64.f);
            float v = 0.f;
#pragma unroll
            for (int j = 0; j < 32; j++) {
                float2 f = up2(h2[j]);
                float d0 = f.x - mu, d1 = f.y - mu;
                v = fmaf(d0, d0, fmaf(d1, d1, v));
            }
            float rr = rsqrtf(v * (1.f / 64.f) + 1e-6f);
#pragma unroll
            for (int j = 0; j < 32; j++) {
                float2 f = up2(h2[j]);
                float y0 = (f.x - mu) * rr * sP[64 + 2 * j] + sP[128 + 2 * j];
                float y1 = (f.y - mu) * rr * sP[64 + 2 * j + 1] + sP[128 + 2 * j + 1];
                sx[(2 * j) * 129 + tid]     = y0 / (1.f + __expf(-y0));
                sx[(2 * j + 1) * 129 + tid] = y1 / (1.f + __expf(-y1));
            }
        }
        __syncthreads();
        for (int li = tid; li < 4096; li += 128) sW[li] = aW2[br * 4096 + li];
        __syncthreads();
        // layer 2
#pragma unroll
        for (int j = 0; j < 32; j++) h2[j] = pk2(sP[192 + 2 * j], sP[192 + 2 * j + 1]);
        for (int i = 0; i < 64; i++) {
            float xv = sx[i * 129 + tid];
            unsigned long long xv2 = pk2(xv, xv);
            const ulonglong2* wr = (const ulonglong2*)(sW + i * 64);
#pragma unroll
            for (int j = 0; j < 16; j++) {
                ulonglong2 q = wr[j];
                fma2(h2[2 * j], xv2, q.x);
                fma2(h2[2 * j + 1], xv2, q.y);
            }
        }
        {
            float mu = 0.f;
#pragma unroll
            for (int j = 0; j < 32; j++) { float2 f = up2(h2[j]); mu += f.x + f.y; }
            mu *= (1.f / 64.f);
            float v = 0.f;
#pragma unroll
            for (int j = 0; j < 32; j++) {
                float2 f = up2(h2[j]);
                float d0 = f.x - mu, d1 = f.y - mu;
                v = fmaf(d0, d0, fmaf(d1, d1, v));
            }
            float rr = rsqrtf(v * (1.f / 64.f) + 1e-6f);
#pragma unroll
            for (int j = 0; j < 32; j++) {
                float2 f = up2(h2[j]);
                float y0 = (f.x - mu) * rr * sP[256 + 2 * j] + sP[320 + 2 * j];
                float y1 = (f.y - mu) * rr * sP[256 + 2 * j + 1] + sP[320 + 2 * j + 1];
                sx[(2 * j) * 129 + tid]     = y0 / (1.f + __expf(-y0));
                sx[(2 * j + 1) * 129 + tid] = y1 / (1.f + __expf(-y1));
            }
        }
        // layer 3 (reads own column only)
        unsigned long long o2[4];
#pragma unroll
        for (int j = 0; j < 4; j++) o2[j] = pk2(sb3[2 * j], sb3[2 * j + 1]);
        for (int i = 0; i < 64; i++) {
            float xv = sx[i * 129 + tid];
            unsigned long long xv2 = pk2(xv, xv);
            const ulonglong2* wr = (const ulonglong2*)(sW3 + i * 8);
            ulonglong2 qa = wr[0], qb = wr[1];
            fma2(o2[0], xv2, qa.x); fma2(o2[1], xv2, qa.y);
            fma2(o2[2], xv2, qb.x); fma2(o2[3], xv2, qb.y);
        }
        float o[8];
#pragma unroll
        for (int j = 0; j < 4; j++) { float2 f = up2(o2[j]); o[2 * j] = f.x; o[2 * j + 1] = f.y; }
#pragma unroll
        for (int j = 0; j < 8; j++) res[j] = br ? res[j] * o[j] : o[j];
    }
    if (act) {
        float4* ap = (float4*)(g_alpha + (size_t)tri * 8);
        ap[0] = make_float4(res[0], res[1], res[2], res[3]);
        ap[1] = make_float4(res[4], res[5], res[6], res[7]);
    }
}

// ---------------- segment softmax + gather-aggregate ----------------
__global__ void k_attn(const int* __restrict__ inv, const int* __restrict__ t1, int E) {
    int e = blockIdx.x * 8 + (threadIdx.x >> 5);
    if (e >= E) return;
    int lane = threadIdx.x & 31;
    int lo = g_seg[e], hi = g_seg[e + 1];
    int h = lane >> 2;
    float m = -1e30f;
    for (int t = lo; t < hi; t++) m = fmaxf(m, g_alpha[t * 8 + h]);
    float s = 0.f;
    for (int t = lo; t < hi; t++) s += __expf(g_alpha[t * 8 + h] - m);
    float inv_s = (s > 0.f) ? 1.f / s : 0.f;
    float acc[16];
#pragma unroll
    for (int j = 0; j < 16; j++) acc[j] = 0.f;
    for (int t = lo; t < hi; t++) {
        int es = inv[t1[t]];
        float w = __expf(g_alpha[t * 8 + h] - m) * inv_s;
        const uint4* vp = (const uint4*)(g_value + (size_t)es * 512 + lane * 16);
        uint4 u0 = vp[0], u1 = vp[1];
        const half2* p0 = (const half2*)&u0;
        const half2* p1 = (const half2*)&u1;
#pragma unroll
        for (int j = 0; j < 4; j++) {
            float2 f0 = __half22float2(p0[j]);
            float2 f1 = __half22float2(p1[j]);
            acc[2 * j]         = fmaf(w, f0.x, acc[2 * j]);
            acc[2 * j + 1]     = fmaf(w, f0.y, acc[2 * j + 1]);
            acc[8 + 2 * j]     = fmaf(w, f1.x, acc[8 + 2 * j]);
            acc[8 + 2 * j + 1] = fmaf(w, f1.y, acc[8 + 2 * j + 1]);
        }
    }
    half2 o[8];
#pragma unroll
    for (int j = 0; j < 8; j++) o[j] = __floats2half2_rn(acc[2 * j], acc[2 * j + 1]);
    uint4* fp = (uint4*)(g_fea + (size_t)e * 512 + lane * 16);
    fp[0] = *(uint4*)&o[0];
    fp[1] = *(uint4*)&o[4];
}

// ---------------- out = fea @ lin_W + lin_b  (pipelined) ----------------
__global__ __launch_bounds__(256, 2) void k_out(const float* __restrict__ linb,
                                                float* __restrict__ out, int M) {
    __shared__ half sA[2][128 * 72];
    __shared__ half sB[2][128 * 72];
    int m0 = blockIdx.x * 128;
    int tid = threadIdx.x, lane = tid & 31, wid = tid >> 5;
    int wm = (wid & 3) * 32, wn = (wid >> 2) * 64;
    int g = lane >> 2, tg = lane & 3;
    int row = tid >> 1, koff = (tid & 1) * 32;
    int erow = min(m0 + row, M - 1);

    float acc[2][8][4];
#pragma unroll
    for (int a = 0; a < 2; a++)
#pragma unroll
        for (int b = 0; b < 8; b++)
#pragma unroll
            for (int c = 0; c < 4; c++) acc[a][b][c] = 0.f;

    {
        const half* srcA = g_fea + (size_t)erow * 512 + koff;
        const half* srcB = g_linWT + row * 512 + koff;
#pragma unroll
        for (int j = 0; j < 4; j++) {
            cp16(&sA[0][row * 72 + koff + j * 8], srcA + j * 8);
            cp16(&sB[0][row * 72 + koff + j * 8], srcB + j * 8);
        }
        CP_COMMIT(); CP_WAIT0();
        __syncthreads();
    }

    for (int kc = 0; kc < 8; kc++) {
        int p = kc & 1;
        if (kc < 7) {
            const half* srcA = g_fea + (size_t)erow * 512 + (kc + 1) * 64 + koff;
            const half* srcB = g_linWT + row * 512 + (kc + 1) * 64 + koff;
#pragma unroll
            for (int j = 0; j < 4; j++) {
                cp16(&sA[1 - p][row * 72 + koff + j * 8], srcA + j * 8);
                cp16(&sB[1 - p][row * 72 + koff + j * 8], srcB + j * 8);
            }
            CP_COMMIT();
        }
        tile_mma(sA[p], sB[p], wm, wn, lane, acc);
        if (kc < 7) { CP_WAIT0(); __syncthreads(); }
    }
#pragma unroll
    for (int mt = 0; mt < 2; mt++)
#pragma unroll
        for (int nt = 0; nt < 8; nt++) {
            int er = m0 + wm + mt * 16 + g;
            int cn = wn + nt * 8 + tg * 2;
            float bb0 = linb[cn], bb1 = linb[cn + 1];
            if (er < M)
                *(float2*)&out[(size_t)er * 128 + cn] =
                    make_float2(acc[mt][nt][0] + bb0, acc[mt][nt][1] + bb1);
            if (er + 8 < M)
                *(float2*)&out[(size_t)(er + 8) * 128 + cn] =
                    make_float2(acc[mt][nt][2] + bb0, acc[mt][nt][3] + bb1);
        }
}

// ---------------- launcher ----------------
extern "C" void kernel_launch(void* const* d_in, const int* in_sizes, int n_in,
                              void* d_out, int out_size) {
    const float* edge_in = (const float*)d_in[0];
    const int*   inv     = (const int*)d_in[1];
    const float* esh     = (const float*)d_in[2];
    const float* elen    = (const float*)d_in[3];
    const int*   t0      = (const int*)d_in[6];
    const int*   t1      = (const int*)d_in[7];
    const float* emb2    = (const float*)d_in[8];
    const float* emb3    = (const float*)d_in[9];
    const float* Wtp     = (const float*)d_in[11];
    const float* rW1     = (const float*)d_in[12];
    const float* rb1     = (const float*)d_in[13];
    const float* rW2     = (const float*)d_in[14];
    const float* rb2     = (const float*)d_in[15];
    const float* aW1     = (const float*)d_in[16];
    const float* ab1     = (const float*)d_in[17];
    const float* ag1     = (const float*)d_in[18];
    const float* abe1    = (const float*)d_in[19];
    const float* aW2     = (const float*)d_in[20];
    const float* ab2     = (const float*)d_in[21];
    const float* ag2     = (const float*)d_in[22];
    const float* abe2    = (const float*)d_in[23];
    const float* aW3     = (const float*)d_in[24];
    const float* ab3     = (const float*)d_in[25];
    const float* linW    = (const float*)d_in[26];
    const float* linb    = (const float*)d_in[27];
    int E = in_sizes[0] / 64;
    int T = in_sizes[6];

    k_prep<<<512, 256>>>(Wtp, rW2, linW);
    k_hidden<<<CDIV(E, 4), 256>>>(elen, rW1, rb1, E);
    k_radial<<<dim3(CDIV(E, 128), 4), 256>>>(rb2, E);
    k_value<<<dim3(CDIV(E, 128), 4), 256>>>(edge_in, esh, E);
    k_seg<<<CDIV(E + 1, 256), 256>>>(t0, E, T);
    k_alpha<<<CDIV(T, 128), 128>>>(emb2, emb3, aW1, ab1, ag1, abe1,
                                   aW2, ab2, ag2, abe2, aW3, ab3, T);
    k_attn<<<CDIV(E, 8), 256>>>(inv, t1, E);
    k_out<<<CDIV(E, 128), 256>>>(linb, (float*)d_out, E);
}

// round 14
// speedup vs baseline: 1.0124x; 1.0124x over previous
#include <cuda_runtime.h>
#include <cuda_fp16.h>
#include <cstdint>

#define CDIV(a,b) (((a)+(b)-1)/(b))

// ---------------- static device scratch ----------------
__device__ __align__(16) half  g_WtpT  [512 * 1024];
__device__ __align__(16) half  g_W2T   [512 * 64];
__device__ __align__(16) half  g_linWT [128 * 512];
__device__ __align__(16) float g_hidden[160000 * 64];
__device__ __align__(16) half  g_radial[160000 * 512];
__device__ __align__(16) half  g_value [160000 * 512];
__device__ __align__(16) float g_alpha [250000 * 8];
__device__              int    g_seg   [160001];
__device__              int    g_tidx  [250000];
__device__ __align__(16) half  g_fea   [160000 * 512];

// ---------------- PTX helpers ----------------
__device__ __forceinline__ void mma_f16(float* c, const uint32_t* a, const uint32_t* b) {
    asm volatile(
        "mma.sync.aligned.m16n8k16.row.col.f32.f16.f16.f32 "
        "{%0,%1,%2,%3},{%4,%5,%6,%7},{%8,%9},{%0,%1,%2,%3};\n"
        : "+f"(c[0]), "+f"(c[1]), "+f"(c[2]), "+f"(c[3])
        : "r"(a[0]), "r"(a[1]), "r"(a[2]), "r"(a[3]), "r"(b[0]), "r"(b[1]));
}

__device__ __forceinline__ void ldsm4(uint32_t* d, const half* p) {
    uint32_t a = (uint32_t)__cvta_generic_to_shared(p);
    asm volatile("ldmatrix.sync.aligned.m8n8.x4.shared.b16 {%0,%1,%2,%3},[%4];\n"
        : "=r"(d[0]), "=r"(d[1]), "=r"(d[2]), "=r"(d[3]) : "r"(a));
}

__device__ __forceinline__ void cp16(void* smem, const void* gmem) {
    uint32_t s = (uint32_t)__cvta_generic_to_shared(smem);
    asm volatile("cp.async.cg.shared.global [%0], [%1], 16;\n" :: "r"(s), "l"(gmem));
}
#define CP_COMMIT() asm volatile("cp.async.commit_group;\n")
#define CP_WAIT0()  asm volatile("cp.async.wait_group 0;\n")
#define CP_WAIT1()  asm volatile("cp.async.wait_group 1;\n")
#define BARW(id)    asm volatile("bar.sync %0, 128;" :: "r"(id) : "memory")

__device__ __forceinline__ uint32_t packh2(float a, float b) {
    half2 h = __floats2half2_rn(a, b);
    return *(uint32_t*)&h;
}

// one 64-deep K-chunk of mma on 128x128 tile; warp covers 32(m)x64(n).
// smem row stride = 72 halfs (144B): ldmatrix row addrs hit 32 distinct banks.
__device__ __forceinline__ void tile_mma(const half* sA, const half* sB,
                                         int wm, int wn, int lane,
                                         float acc[2][8][4]) {
    int r15 = lane & 15;
    int a_k8 = ((lane >> 4) & 1) * 8;
    int b_r8 = ((lane >> 4) & 1) * 8;
    int b_k8 = lane & 8;
    int l7 = lane & 7;
#pragma unroll
    for (int ks = 0; ks < 4; ks++) {
        uint32_t af[2][4];
#pragma unroll
        for (int mt = 0; mt < 2; mt++)
            ldsm4(af[mt], sA + (wm + mt * 16 + r15) * 72 + ks * 16 + a_k8);
        uint32_t bf[4][4];
#pragma unroll
        for (int np = 0; np < 4; np++)
            ldsm4(bf[np], sB + (wn + np * 16 + b_r8 + l7) * 72 + ks * 16 + b_k8);
#pragma unroll
        for (int np = 0; np < 4; np++) {
            mma_f16(acc[0][2 * np],     af[0], &bf[np][0]);
            mma_f16(acc[0][2 * np + 1], af[0], &bf[np][2]);
            mma_f16(acc[1][2 * np],     af[1], &bf[np][0]);
            mma_f16(acc[1][2 * np + 1], af[1], &bf[np][2]);
        }
    }
}

// ---------------- weight prep ----------------
__global__ void k_prep(const float* __restrict__ Wtp, const float* __restrict__ W2,
                       const float* __restrict__ linW) {
    int i = blockIdx.x * blockDim.x + threadIdx.x;
    int stride = gridDim.x * blockDim.x;
    for (int idx = i; idx < 512 * 1024; idx += stride) {
        int n = idx >> 10, k = idx & 1023;
        g_WtpT[idx] = __float2half_rn(Wtp[k * 512 + n]);
    }
    for (int idx = i; idx < 512 * 64; idx += stride) {
        int n = idx >> 6, k = idx & 63;
        g_W2T[idx] = __float2half_rn(W2[k * 512 + n]);
    }
    for (int idx = i; idx < 128 * 512; idx += stride) {
        int n = idx >> 9, k = idx & 511;
        g_linWT[idx] = __float2half_rn(linW[k * 128 + n]);
    }
}

// ---------------- hidden = silu(emb @ W1 + b1) ----------------
__global__ void k_hidden(const float* __restrict__ emb, const float* __restrict__ W1,
                         const float* __restrict__ b1, int E) {
    __shared__ float s_e[4][64];
    int tid = threadIdx.x;
    int slot = tid >> 6, j = tid & 63;
    int e = blockIdx.x * 4 + slot;
    int ec = min(e, E - 1);
    s_e[slot][j] = emb[ec * 64 + j];
    __syncthreads();
    float acc = b1[j];
#pragma unroll 8
    for (int i = 0; i < 64; i++) acc = fmaf(s_e[slot][i], W1[i * 64 + j], acc);
    float y = acc / (1.f + __expf(-acc));
    if (e < E) g_hidden[e * 64 + j] = y;
}

// ---------------- radial = hidden @ W2 + b2  (K=64 mma) ----------------
__global__ __launch_bounds__(256) void k_radial(const float* __restrict__ b2, int M) {
    __shared__ half sA[128 * 72];
    __shared__ half sB[128 * 72];
    int m0 = blockIdx.x * 128, n0 = blockIdx.y * 128;
    int tid = threadIdx.x, lane = tid & 31, wid = tid >> 5;
    int wm = (wid & 3) * 32, wn = (wid >> 2) * 64;
    int g = lane >> 2, tg = lane & 3;
    int row = tid >> 1, koff = (tid & 1) * 32;
    int erow = min(m0 + row, M - 1);

    float acc[2][8][4];
#pragma unroll
    for (int a = 0; a < 2; a++)
#pragma unroll
        for (int b = 0; b < 8; b++)
#pragma unroll
            for (int c = 0; c < 4; c++) acc[a][b][c] = 0.f;

    const float4* hp = (const float4*)(g_hidden + erow * 64 + koff);
#pragma unroll
    for (int j = 0; j < 8; j++) {
        float4 v = hp[j];
        *(half2*)&sA[row * 72 + koff + j * 4]     = __floats2half2_rn(v.x, v.y);
        *(half2*)&sA[row * 72 + koff + j * 4 + 2] = __floats2half2_rn(v.z, v.w);
    }
    {
        const uint4* s = (const uint4*)(g_W2T + (n0 + row) * 64 + koff);
        uint4* d = (uint4*)&sB[row * 72 + koff];
        d[0] = s[0]; d[1] = s[1]; d[2] = s[2]; d[3] = s[3];
    }
    __syncthreads();
    tile_mma(sA, sB, wm, wn, lane, acc);

#pragma unroll
    for (int mt = 0; mt < 2; mt++)
#pragma unroll
        for (int nt = 0; nt < 8; nt++) {
            int er = m0 + wm + mt * 16 + g;
            int cn = n0 + wn + nt * 8 + tg * 2;
            float bb0 = b2[cn], bb1 = b2[cn + 1];
            if (er < M)
                *(half2*)&g_radial[er * 512 + cn] =
                    __floats2half2_rn(acc[mt][nt][0] + bb0, acc[mt][nt][1] + bb1);
            if (er + 8 < M)
                *(half2*)&g_radial[(er + 8) * 512 + cn] =
                    __floats2half2_rn(acc[mt][nt][2] + bb0, acc[mt][nt][3] + bb1);
        }
}

// ---------------- value = (z @ W_tp) * radial ----------------
// K=1024, register-built A, 3-stage cp.async ring, half-CTA named barriers.
// Warps 0-3 (group 0) own B rows [0,64); warps 4-7 (group 1) rows [64,128).
// Each group has a PRIVATE sE copy so NO smem crosses the group boundary:
// the two halves run fully desynchronized.
__global__ __launch_bounds__(256, 2) void k_value(const float* __restrict__ ein,
                                                  const float* __restrict__ esh, int M) {
    __shared__ half  sB[3][128 * 72];
    __shared__ float sE[2][3][128 * 4];
    int m0 = blockIdx.x * 128, n0 = blockIdx.y * 128;
    int tid = threadIdx.x, lane = tid & 31, wid = tid >> 5;
    int wm = (wid & 3) * 32, wn = (wid >> 2) * 64;
    int g = lane >> 2, tg = lane & 3;
    int row = tid >> 1, koff = (tid & 1) * 32;
    int grp = wid >> 2;
    int bar_id = 1 + grp;

    int b_r8 = ((lane >> 4) & 1) * 8;
    int b_k8 = lane & 8;
    int l7 = lane & 7;

    // local + clamped-global A-fragment rows (2 m-tiles x 2 row-halves)
    int lr[4], r[4];
#pragma unroll
    for (int q = 0; q < 4; q++) {
        lr[q] = wm + g + ((q & 1) ? 8 : 0) + ((q >> 1) ? 16 : 0);
        r[q]  = min(m0 + lr[q], M - 1);
    }

    // SH columns owned by this thread (fixed across all K)
    float shf[4][4];
#pragma unroll
    for (int q = 0; q < 4; q++) {
        const float* sp = esh + r[q] * 16;
        shf[q][0] = __ldg(&sp[tg * 2]);
        shf[q][1] = __ldg(&sp[tg * 2 + 1]);
        shf[q][2] = __ldg(&sp[tg * 2 + 8]);
        shf[q][3] = __ldg(&sp[tg * 2 + 9]);
    }

    // stage loaders: B row tid>>1 (group-local rows), sE group-private full copy
    int e_row = min(m0 + wm + lane, M - 1);
    auto load_stage = [&](int s, int kc) {
        const half* src = g_WtpT + (n0 + row) * 1024 + kc * 64 + koff;
        half* dst = &sB[s][row * 72 + koff];
#pragma unroll
        for (int j = 0; j < 4; j++) cp16(dst + j * 8, src + j * 8);
        cp16(&sE[grp][s][(wm + lane) * 4], ein + (size_t)e_row * 64 + kc * 4);
    };

    float acc[2][8][4];
#pragma unroll
    for (int a = 0; a < 2; a++)
#pragma unroll
        for (int b = 0; b < 8; b++)
#pragma unroll
            for (int c = 0; c < 4; c++) acc[a][b][c] = 0.f;

    // prologue: stage chunks 0 and 1
    load_stage(0, 0); CP_COMMIT();
    load_stage(1, 1); CP_COMMIT();
    CP_WAIT1();               // stage 0 complete (this thread's loads)
    BARW(bar_id);             // half-CTA: all producers for our rows done

    for (int kc = 0; kc < 16; kc++) {
        int p = kc % 3;
        if (kc < 14) { load_stage((kc + 2) % 3, kc + 2); CP_COMMIT(); }

        // ein values for this chunk from the group-private sE copy
        float4 ev[4];
#pragma unroll
        for (int q = 0; q < 4; q++)
            ev[q] = *(const float4*)&sE[grp][p][lr[q] * 4];

        const half* sBp = sB[p];
#pragma unroll
        for (int ks = 0; ks < 4; ks++) {
            float e0 = ((const float*)&ev[0])[ks];
            float e1 = ((const float*)&ev[1])[ks];
            float e2 = ((const float*)&ev[2])[ks];
            float e3 = ((const float*)&ev[3])[ks];
            uint32_t af[2][4];
            af[0][0] = packh2(e0 * shf[0][0], e0 * shf[0][1]);
            af[0][1] = packh2(e1 * shf[1][0], e1 * shf[1][1]);
            af[0][2] = packh2(e0 * shf[0][2], e0 * shf[0][3]);
            af[0][3] = packh2(e1 * shf[1][2], e1 * shf[1][3]);
            af[1][0] = packh2(e2 * shf[2][0], e2 * shf[2][1]);
            af[1][1] = packh2(e3 * shf[3][0], e3 * shf[3][1]);
            af[1][2] = packh2(e2 * shf[2][2], e2 * shf[2][3]);
            af[1][3] = packh2(e3 * shf[3][2], e3 * shf[3][3]);

            uint32_t bf[4][4];
#pragma unroll
            for (int np = 0; np < 4; np++)
                ldsm4(bf[np], sBp + (wn + np * 16 + b_r8 + l7) * 72 + ks * 16 + b_k8);
#pragma unroll
            for (int np = 0; np < 4; np++) {
                mma_f16(acc[0][2 * np],     af[0], &bf[np][0]);
                mma_f16(acc[0][2 * np + 1], af[0], &bf[np][2]);
                mma_f16(acc[1][2 * np],     af[1], &bf[np][0]);
                mma_f16(acc[1][2 * np + 1], af[1], &bf[np][2]);
            }
        }
        if (kc < 15) {
            CP_WAIT1();       // next stage complete (lookahead stage may still fly)
            BARW(bar_id);     // half-CTA barrier only
        }
    }

    // epilogue: value = acc * radial (radial fp16, incl. bias)
#pragma unroll
    for (int mt = 0; mt < 2; mt++)
#pragma unroll
        for (int nt = 0; nt < 8; nt++) {
            int er = m0 + wm + mt * 16 + g;
            int cn = n0 + wn + nt * 8 + tg * 2;
            if (er < M) {
                float2 rr = __half22float2(*(const half2*)&g_radial[er * 512 + cn]);
                *(half2*)&g_value[er * 512 + cn] =
                    __floats2half2_rn(acc[mt][nt][0] * rr.x, acc[mt][nt][1] * rr.y);
            }
            if (er + 8 < M) {
                float2 rr = __half22float2(*(const half2*)&g_radial[(er + 8) * 512 + cn]);
                *(half2*)&g_value[(er + 8) * 512 + cn] =
                    __floats2half2_rn(acc[mt][nt][2] * rr.x, acc[mt][nt][3] * rr.y);
            }
        }
}

// ---------------- segment offsets (triple_idx0 sorted) ----------------
__global__ void k_seg(const int* __restrict__ t0, int E, int T) {
    int e = blockIdx.x * blockDim.x + threadIdx.x;
    if (e > E) return;
    int lo = 0, hi = T;
    while (lo < hi) {
        int mid = (lo + hi) >> 1;
        if (t0[mid] < e) lo = mid + 1; else hi = mid;
    }
    g_seg[e] = lo;
}

// ---------------- fused gather index: g_tidx[t] = inv[t1[t]] ----------------
__global__ void k_tidx(const int* __restrict__ t1, const int* __restrict__ inv, int T) {
    int t = blockIdx.x * blockDim.x + threadIdx.x;
    if (t < T) g_tidx[t] = inv[t1[t]];
}

// ---------------- alpha MLPs (fp32, thread-per-triplet) ----------------
__global__ __launch_bounds__(128) void k_alpha(
    const float* __restrict__ emb2, const float* __restrict__ emb3,
    const float* __restrict__ aW1, const float* __restrict__ ab1,
    const float* __restrict__ ag1, const float* __restrict__ abe1,
    const float* __restrict__ aW2, const float* __restrict__ ab2,
    const float* __restrict__ ag2, const float* __restrict__ abe2,
    const float* __restrict__ aW3, const float* __restrict__ ab3, int T) {
    __shared__ float sW[64 * 64];
    __shared__ float sW3[64 * 8];
    __shared__ float sP[6 * 64];
    __shared__ float sb3[8];
    __shared__ float sx[64 * 129];
    int tid = threadIdx.x;
    int base = blockIdx.x * 128;
    int tri = base + tid;
    bool act = tri < T;
    float res[8];

    for (int br = 0; br < 2; br++) {
        const float* emb = br ? emb3 : emb2;
        __syncthreads();
        for (int li = tid; li < 128 * 64; li += 128) {
            int r = li >> 6, c = li & 63;
            int tt = min(base + r, T - 1);
            sx[c * 129 + r] = emb[tt * 64 + c];
        }
        for (int li = tid; li < 4096; li += 128) sW[li] = aW1[br * 4096 + li];
        for (int li = tid; li < 512; li += 128) sW3[li] = aW3[br * 512 + li];
        if (tid < 64) {
            sP[tid] = ab1[br * 64 + tid];        sP[64 + tid] = ag1[br * 64 + tid];
            sP[128 + tid] = abe1[br * 64 + tid]; sP[192 + tid] = ab2[br * 64 + tid];
            sP[256 + tid] = ag2[br * 64 + tid];  sP[320 + tid] = abe2[br * 64 + tid];
        }
        if (tid < 8) sb3[tid] = ab3[br * 8 + tid];
        __syncthreads();

        const float4* sW4 = (const float4*)sW;
        float h[64];
        // layer 1
#pragma unroll
        for (int j = 0; j < 64; j++) h[j] = sP[j];
        for (int i = 0; i < 64; i++) {
            float xv = sx[i * 129 + tid];
#pragma unroll
            for (int j4 = 0; j4 < 16; j4++) {
                float4 w = sW4[i * 16 + j4];
                h[4 * j4]     = fmaf(xv, w.x, h[4 * j4]);
                h[4 * j4 + 1] = fmaf(xv, w.y, h[4 * j4 + 1]);
                h[4 * j4 + 2] = fmaf(xv, w.z, h[4 * j4 + 2]);
                h[4 * j4 + 3] = fmaf(xv, w.w, h[4 * j4 + 3]);
            }
        }
        {
            float mu = 0.f;
#pragma unroll
            for (int j = 0; j < 64; j++) mu += h[j];
            mu *= (1.f / 64.f);
            float v = 0.f;
#pragma unroll
            for (int j = 0; j < 64; j++) { float d = h[j] - mu; v = fmaf(d, d, v); }
            float rr = rsqrtf(v * (1.f / 64.f) + 1e-6f);
#pragma unroll
            for (int j = 0; j < 64; j++) {
                float y = (h[j] - mu) * rr * sP[64 + j] + sP[128 + j];
                sx[j * 129 + tid] = y / (1.f + __expf(-y));
            }
        }
        __syncthreads();
        for (int li = tid; li < 4096; li += 128) sW[li] = aW2[br * 4096 + li];
        __syncthreads();
        // layer 2
#pragma unroll
        for (int j = 0; j < 64; j++) h[j] = sP[192 + j];
        for (int i = 0; i < 64; i++) {
            float xv = sx[i * 129 + tid];
#pragma unroll
            for (int j4 = 0; j4 < 16; j4++) {
                float4 w = sW4[i * 16 + j4];
                h[4 * j4]     = fmaf(xv, w.x, h[4 * j4]);
                h[4 * j4 + 1] = fmaf(xv, w.y, h[4 * j4 + 1]);
                h[4 * j4 + 2] = fmaf(xv, w.z, h[4 * j4 + 2]);
                h[4 * j4 + 3] = fmaf(xv, w.w, h[4 * j4 + 3]);
            }
        }
        {
            float mu = 0.f;
#pragma unroll
            for (int j = 0; j < 64; j++) mu += h[j];
            mu *= (1.f / 64.f);
            float v = 0.f;
#pragma unroll
            for (int j = 0; j < 64; j++) { float d = h[j] - mu; v = fmaf(d, d, v); }
            float rr = rsqrtf(v * (1.f / 64.f) + 1e-6f);
#pragma unroll
            for (int j = 0; j < 64; j++) {
                float y = (h[j] - mu) * rr * sP[256 + j] + sP[320 + j];
                sx[j * 129 + tid] = y / (1.f + __expf(-y));
            }
        }
        // layer 3 (reads own column only)
        const float4* sW34 = (const float4*)sW3;
        float o[8];
#pragma unroll
        for (int j = 0; j < 8; j++) o[j] = sb3[j];
        for (int i = 0; i < 64; i++) {
            float xv = sx[i * 129 + tid];
            float4 w0 = sW34[i * 2], w1 = sW34[i * 2 + 1];
            o[0] = fmaf(xv, w0.x, o[0]); o[1] = fmaf(xv, w0.y, o[1]);
            o[2] = fmaf(xv, w0.z, o[2]); o[3] = fmaf(xv, w0.w, o[3]);
            o[4] = fmaf(xv, w1.x, o[4]); o[5] = fmaf(xv, w1.y, o[5]);
            o[6] = fmaf(xv, w1.z, o[6]); o[7] = fmaf(xv, w1.w, o[7]);
        }
#pragma unroll
        for (int j = 0; j < 8; j++) res[j] = br ? res[j] * o[j] : o[j];
    }
    if (act) {
        float4* ap = (float4*)(g_alpha + (size_t)tri * 8);
        ap[0] = make_float4(res[0], res[1], res[2], res[3]);
        ap[1] = make_float4(res[4], res[5], res[6], res[7]);
    }
}

// ---------------- segment softmax + gather-aggregate ----------------
__global__ void k_attn(int E) {
    int e = blockIdx.x * 8 + (threadIdx.x >> 5);
    if (e >= E) return;
    int lane = threadIdx.x & 31;
    int lo = g_seg[e], hi = g_seg[e + 1];
    int h = lane >> 2;
    float m = -1e30f;
    for (int t = lo; t < hi; t++) m = fmaxf(m, g_alpha[t * 8 + h]);
    float s = 0.f;
    for (int t = lo; t < hi; t++) s += __expf(g_alpha[t * 8 + h] - m);
    float inv_s = (s > 0.f) ? 1.f / s : 0.f;
    float acc[16];
#pragma unroll
    for (int j = 0; j < 16; j++) acc[j] = 0.f;
    for (int t = lo; t < hi; t++) {
        int es = g_tidx[t];
        float w = __expf(g_alpha[t * 8 + h] - m) * inv_s;
        const uint4* vp = (const uint4*)(g_value + (size_t)es * 512 + lane * 16);
        uint4 u0 = vp[0], u1 = vp[1];
        const half2* p0 = (const half2*)&u0;
        const half2* p1 = (const half2*)&u1;
#pragma unroll
        for (int j = 0; j < 4; j++) {
            float2 f0 = __half22float2(p0[j]);
            float2 f1 = __half22float2(p1[j]);
            acc[2 * j]         = fmaf(w, f0.x, acc[2 * j]);
            acc[2 * j + 1]     = fmaf(w, f0.y, acc[2 * j + 1]);
            acc[8 + 2 * j]     = fmaf(w, f1.x, acc[8 + 2 * j]);
            acc[8 + 2 * j + 1] = fmaf(w, f1.y, acc[8 + 2 * j + 1]);
        }
    }
    half2 o[8];
#pragma unroll
    for (int j = 0; j < 8; j++) o[j] = __floats2half2_rn(acc[2 * j], acc[2 * j + 1]);
    uint4* fp = (uint4*)(g_fea + (size_t)e * 512 + lane * 16);
    fp[0] = *(uint4*)&o[0];
    fp[1] = *(uint4*)&o[4];
}

// ---------------- out = fea @ lin_W + lin_b  (pipelined) ----------------
__global__ __launch_bounds__(256, 2) void k_out(const float* __restrict__ linb,
                                                float* __restrict__ out, int M) {
    __shared__ half sA[2][128 * 72];
    __shared__ half sB[2][128 * 72];
    int m0 = blockIdx.x * 128;
    int tid = threadIdx.x, lane = tid & 31, wid = tid >> 5;
    int wm = (wid & 3) * 32, wn = (wid >> 2) * 64;
    int g = lane >> 2, tg = lane & 3;
    int row = tid >> 1, koff = (tid & 1) * 32;
    int erow = min(m0 + row, M - 1);

    float acc[2][8][4];
#pragma unroll
    for (int a = 0; a < 2; a++)
#pragma unroll
        for (int b = 0; b < 8; b++)
#pragma unroll
            for (int c = 0; c < 4; c++) acc[a][b][c] = 0.f;

    {
        const half* srcA = g_fea + (size_t)erow * 512 + koff;
        const half* srcB = g_linWT + row * 512 + koff;
#pragma unroll
        for (int j = 0; j < 4; j++) {
            cp16(&sA[0][row * 72 + koff + j * 8], srcA + j * 8);
            cp16(&sB[0][row * 72 + koff + j * 8], srcB + j * 8);
        }
        CP_COMMIT(); CP_WAIT0();
        __syncthreads();
    }

    for (int kc = 0; kc < 8; kc++) {
        int p = kc & 1;
        if (kc < 7) {
            const half* srcA = g_fea + (size_t)erow * 512 + (kc + 1) * 64 + koff;
            const half* srcB = g_linWT + row * 512 + (kc + 1) * 64 + koff;
#pragma unroll
            for (int j = 0; j < 4; j++) {
                cp16(&sA[1 - p][row * 72 + koff + j * 8], srcA + j * 8);
                cp16(&sB[1 - p][row * 72 + koff + j * 8], srcB + j * 8);
            }
            CP_COMMIT();
        }
        tile_mma(sA[p], sB[p], wm, wn, lane, acc);
        if (kc < 7) { CP_WAIT0(); __syncthreads(); }
    }
#pragma unroll
    for (int mt = 0; mt < 2; mt++)
#pragma unroll
        for (int nt = 0; nt < 8; nt++) {
            int er = m0 + wm + mt * 16 + g;
            int cn = wn + nt * 8 + tg * 2;
            float bb0 = linb[cn], bb1 = linb[cn + 1];
            if (er < M)
                *(float2*)&out[(size_t)er * 128 + cn] =
                    make_float2(acc[mt][nt][0] + bb0, acc[mt][nt][1] + bb1);
            if (er + 8 < M)
                *(float2*)&out[(size_t)(er + 8) * 128 + cn] =
                    make_float2(acc[mt][nt][2] + bb0, acc[mt][nt][3] + bb1);
        }
}

// ---------------- launcher ----------------
extern "C" void kernel_launch(void* const* d_in, const int* in_sizes, int n_in,
                              void* d_out, int out_size) {
    const float* edge_in = (const float*)d_in[0];
    const int*   inv     = (const int*)d_in[1];
    const float* esh     = (const float*)d_in[2];
    const float* elen    = (const float*)d_in[3];
    const int*   t0      = (const int*)d_in[6];
    const int*   t1      = (const int*)d_in[7];
    const float* emb2    = (const float*)d_in[8];
    const float* emb3    = (const float*)d_in[9];
    const float* Wtp     = (const float*)d_in[11];
    const float* rW1     = (const float*)d_in[12];
    const float* rb1     = (const float*)d_in[13];
    const float* rW2     = (const float*)d_in[14];
    const float* rb2     = (const float*)d_in[15];
    const float* aW1     = (const float*)d_in[16];
    const float* ab1     = (const float*)d_in[17];
    const float* ag1     = (const float*)d_in[18];
    const float* abe1    = (const float*)d_in[19];
    const float* aW2     = (const float*)d_in[20];
    const float* ab2     = (const float*)d_in[21];
    const float* ag2     = (const float*)d_in[22];
    const float* abe2    = (const float*)d_in[23];
    const float* aW3     = (const float*)d_in[24];
    const float* ab3     = (const float*)d_in[25];
    const float* linW    = (const float*)d_in[26];
    const float* linb    = (const float*)d_in[27];
    int E = in_sizes[0] / 64;
    int T = in_sizes[6];

    k_prep<<<512, 256>>>(Wtp, rW2, linW);
    k_hidden<<<CDIV(E, 4), 256>>>(elen, rW1, rb1, E);
    k_radial<<<dim3(CDIV(E, 128), 4), 256>>>(rb2, E);
    k_value<<<dim3(CDIV(E, 128), 4), 256>>>(edge_in, esh, E);
    k_seg<<<CDIV(E + 1, 256), 256>>>(t0, E, T);
    k_tidx<<<CDIV(T, 256), 256>>>(t1, inv, T);
    k_alpha<<<CDIV(T, 128), 128>>>(emb2, emb3, aW1, ab1, ag1, abe1,
                                   aW2, ab2, ag2, abe2, aW3, ab3, T);
    k_attn<<<CDIV(E, 8), 256>>>(E);
    k_out<<<CDIV(E, 128), 256>>>(linb, (float*)d_out, E);
}

// round 15
// speedup vs baseline: 1.0508x; 1.0379x over previous
#include <cuda_runtime.h>
#include <cuda_fp16.h>
#include <cstdint>

#define CDIV(a,b) (((a)+(b)-1)/(b))

// ---------------- static device scratch ----------------
__device__ __align__(16) half  g_WtpT  [512 * 1024];
__device__ __align__(16) half  g_W2T   [512 * 64];
__device__ __align__(16) half  g_linWT [128 * 512];
__device__ __align__(16) float g_hidden[160000 * 64];
__device__ __align__(16) half  g_radial[160000 * 512];
__device__ __align__(16) half  g_value [160000 * 512];
__device__ __align__(16) float g_alpha [250000 * 8];
__device__              int    g_seg   [160001];
__device__              int    g_tidx  [250000];
__device__ __align__(16) half  g_fea   [160000 * 512];

// ---------------- PTX helpers ----------------
__device__ __forceinline__ void mma_f16(float* c, const uint32_t* a, const uint32_t* b) {
    asm volatile(
        "mma.sync.aligned.m16n8k16.row.col.f32.f16.f16.f32 "
        "{%0,%1,%2,%3},{%4,%5,%6,%7},{%8,%9},{%0,%1,%2,%3};\n"
        : "+f"(c[0]), "+f"(c[1]), "+f"(c[2]), "+f"(c[3])
        : "r"(a[0]), "r"(a[1]), "r"(a[2]), "r"(a[3]), "r"(b[0]), "r"(b[1]));
}

__device__ __forceinline__ void ldsm4(uint32_t* d, const half* p) {
    uint32_t a = (uint32_t)__cvta_generic_to_shared(p);
    asm volatile("ldmatrix.sync.aligned.m8n8.x4.shared.b16 {%0,%1,%2,%3},[%4];\n"
        : "=r"(d[0]), "=r"(d[1]), "=r"(d[2]), "=r"(d[3]) : "r"(a));
}

__device__ __forceinline__ void cp16(void* smem, const void* gmem) {
    uint32_t s = (uint32_t)__cvta_generic_to_shared(smem);
    asm volatile("cp.async.cg.shared.global [%0], [%1], 16;\n" :: "r"(s), "l"(gmem));
}
#define CP_COMMIT() asm volatile("cp.async.commit_group;\n")
#define CP_WAIT0()  asm volatile("cp.async.wait_group 0;\n")
#define CP_WAIT1()  asm volatile("cp.async.wait_group 1;\n")

__device__ __forceinline__ uint32_t packh2(float a, float b) {
    half2 h = __floats2half2_rn(a, b);
    return *(uint32_t*)&h;
}

// one 64-deep K-chunk of mma on 128x128 tile; warp covers 32(m)x64(n).
// smem row stride = 72 halfs (144B): ldmatrix row addrs hit 32 distinct banks.
__device__ __forceinline__ void tile_mma(const half* sA, const half* sB,
                                         int wm, int wn, int lane,
                                         float acc[2][8][4]) {
    int r15 = lane & 15;
    int a_k8 = ((lane >> 4) & 1) * 8;
    int b_r8 = ((lane >> 4) & 1) * 8;
    int b_k8 = lane & 8;
    int l7 = lane & 7;
#pragma unroll
    for (int ks = 0; ks < 4; ks++) {
        uint32_t af[2][4];
#pragma unroll
        for (int mt = 0; mt < 2; mt++)
            ldsm4(af[mt], sA + (wm + mt * 16 + r15) * 72 + ks * 16 + a_k8);
        uint32_t bf[4][4];
#pragma unroll
        for (int np = 0; np < 4; np++)
            ldsm4(bf[np], sB + (wn + np * 16 + b_r8 + l7) * 72 + ks * 16 + b_k8);
#pragma unroll
        for (int np = 0; np < 4; np++) {
            mma_f16(acc[0][2 * np],     af[0], &bf[np][0]);
            mma_f16(acc[0][2 * np + 1], af[0], &bf[np][2]);
            mma_f16(acc[1][2 * np],     af[1], &bf[np][0]);
            mma_f16(acc[1][2 * np + 1], af[1], &bf[np][2]);
        }
    }
}

// ---------------- weight prep ----------------
__global__ void k_prep(const float* __restrict__ Wtp, const float* __restrict__ W2,
                       const float* __restrict__ linW) {
    int i = blockIdx.x * blockDim.x + threadIdx.x;
    int stride = gridDim.x * blockDim.x;
    for (int idx = i; idx < 512 * 1024; idx += stride) {
        int n = idx >> 10, k = idx & 1023;
        g_WtpT[idx] = __float2half_rn(Wtp[k * 512 + n]);
    }
    for (int idx = i; idx < 512 * 64; idx += stride) {
        int n = idx >> 6, k = idx & 63;
        g_W2T[idx] = __float2half_rn(W2[k * 512 + n]);
    }
    for (int idx = i; idx < 128 * 512; idx += stride) {
        int n = idx >> 9, k = idx & 511;
        g_linWT[idx] = __float2half_rn(linW[k * 128 + n]);
    }
}

// ---------------- hidden = silu(emb @ W1 + b1) ----------------
__global__ void k_hidden(const float* __restrict__ emb, const float* __restrict__ W1,
                         const float* __restrict__ b1, int E) {
    __shared__ float s_e[4][64];
    int tid = threadIdx.x;
    int slot = tid >> 6, j = tid & 63;
    int e = blockIdx.x * 4 + slot;
    int ec = min(e, E - 1);
    s_e[slot][j] = emb[ec * 64 + j];
    __syncthreads();
    float acc = b1[j];
#pragma unroll 8
    for (int i = 0; i < 64; i++) acc = fmaf(s_e[slot][i], W1[i * 64 + j], acc);
    float y = acc / (1.f + __expf(-acc));
    if (e < E) g_hidden[e * 64 + j] = y;
}

// ---------------- radial = hidden @ W2 + b2  (K=64 mma) ----------------
__global__ __launch_bounds__(256) void k_radial(const float* __restrict__ b2, int M) {
    __shared__ half sA[128 * 72];
    __shared__ half sB[128 * 72];
    int m0 = blockIdx.x * 128, n0 = blockIdx.y * 128;
    int tid = threadIdx.x, lane = tid & 31, wid = tid >> 5;
    int wm = (wid & 3) * 32, wn = (wid >> 2) * 64;
    int g = lane >> 2, tg = lane & 3;
    int row = tid >> 1, koff = (tid & 1) * 32;
    int erow = min(m0 + row, M - 1);

    float acc[2][8][4];
#pragma unroll
    for (int a = 0; a < 2; a++)
#pragma unroll
        for (int b = 0; b < 8; b++)
#pragma unroll
            for (int c = 0; c < 4; c++) acc[a][b][c] = 0.f;

    const float4* hp = (const float4*)(g_hidden + erow * 64 + koff);
#pragma unroll
    for (int j = 0; j < 8; j++) {
        float4 v = hp[j];
        *(half2*)&sA[row * 72 + koff + j * 4]     = __floats2half2_rn(v.x, v.y);
        *(half2*)&sA[row * 72 + koff + j * 4 + 2] = __floats2half2_rn(v.z, v.w);
    }
    {
        const uint4* s = (const uint4*)(g_W2T + (n0 + row) * 64 + koff);
        uint4* d = (uint4*)&sB[row * 72 + koff];
        d[0] = s[0]; d[1] = s[1]; d[2] = s[2]; d[3] = s[3];
    }
    __syncthreads();
    tile_mma(sA, sB, wm, wn, lane, acc);

#pragma unroll
    for (int mt = 0; mt < 2; mt++)
#pragma unroll
        for (int nt = 0; nt < 8; nt++) {
            int er = m0 + wm + mt * 16 + g;
            int cn = n0 + wn + nt * 8 + tg * 2;
            float bb0 = b2[cn], bb1 = b2[cn + 1];
            if (er < M)
                *(half2*)&g_radial[er * 512 + cn] =
                    __floats2half2_rn(acc[mt][nt][0] + bb0, acc[mt][nt][1] + bb1);
            if (er + 8 < M)
                *(half2*)&g_radial[(er + 8) * 512 + cn] =
                    __floats2half2_rn(acc[mt][nt][2] + bb0, acc[mt][nt][3] + bb1);
        }
}

// ---------------- value = (z @ W_tp) * radial ----------------
// K=1024, register-built A, 3-stage cp.async ring (B tile + ein slice per stage)
// (round-12 build: measured 612us standalone)
__global__ __launch_bounds__(256, 2) void k_value(const float* __restrict__ ein,
                                                  const float* __restrict__ esh, int M) {
    __shared__ half  sB[3][128 * 72];
    __shared__ float sE[3][128 * 4];
    int m0 = blockIdx.x * 128, n0 = blockIdx.y * 128;
    int tid = threadIdx.x, lane = tid & 31, wid = tid >> 5;
    int wm = (wid & 3) * 32, wn = (wid >> 2) * 64;
    int g = lane >> 2, tg = lane & 3;
    int row = tid >> 1, koff = (tid & 1) * 32;

    int b_r8 = ((lane >> 4) & 1) * 8;
    int b_k8 = lane & 8;
    int l7 = lane & 7;

    // local + clamped-global A-fragment rows (2 m-tiles x 2 row-halves)
    int lr[4], r[4];
#pragma unroll
    for (int q = 0; q < 4; q++) {
        lr[q] = wm + g + ((q & 1) ? 8 : 0) + ((q >> 1) ? 16 : 0);
        r[q]  = min(m0 + lr[q], M - 1);
    }

    // SH columns owned by this thread (fixed across all K)
    float shf[4][4];
#pragma unroll
    for (int q = 0; q < 4; q++) {
        const float* sp = esh + r[q] * 16;
        shf[q][0] = __ldg(&sp[tg * 2]);
        shf[q][1] = __ldg(&sp[tg * 2 + 1]);
        shf[q][2] = __ldg(&sp[tg * 2 + 8]);
        shf[q][3] = __ldg(&sp[tg * 2 + 9]);
    }

    // stage loaders
    int e_row = min(m0 + (tid & 127), M - 1);   // threads 0..127 load ein rows
    auto load_stage = [&](int s, int kc) {
        const half* src = g_WtpT + (n0 + row) * 1024 + kc * 64 + koff;
        half* dst = &sB[s][row * 72 + koff];
#pragma unroll
        for (int j = 0; j < 4; j++) cp16(dst + j * 8, src + j * 8);
        if (tid < 128)
            cp16(&sE[s][tid * 4], ein + (size_t)e_row * 64 + kc * 4);
    };

    float acc[2][8][4];
#pragma unroll
    for (int a = 0; a < 2; a++)
#pragma unroll
        for (int b = 0; b < 8; b++)
#pragma unroll
            for (int c = 0; c < 4; c++) acc[a][b][c] = 0.f;

    // prologue: stage chunks 0 and 1
    load_stage(0, 0); CP_COMMIT();
    load_stage(1, 1); CP_COMMIT();
    CP_WAIT1();               // stage 0 complete
    __syncthreads();

    for (int kc = 0; kc < 16; kc++) {
        int p = kc % 3;
        if (kc < 14) { load_stage((kc + 2) % 3, kc + 2); CP_COMMIT(); }

        // ein values for this chunk from smem (broadcast LDS.128)
        float4 ev[4];
#pragma unroll
        for (int q = 0; q < 4; q++)
            ev[q] = *(const float4*)&sE[p][lr[q] * 4];

        const half* sBp = sB[p];
#pragma unroll
        for (int ks = 0; ks < 4; ks++) {
            float e0 = ((const float*)&ev[0])[ks];
            float e1 = ((const float*)&ev[1])[ks];
            float e2 = ((const float*)&ev[2])[ks];
            float e3 = ((const float*)&ev[3])[ks];
            uint32_t af[2][4];
            af[0][0] = packh2(e0 * shf[0][0], e0 * shf[0][1]);
            af[0][1] = packh2(e1 * shf[1][0], e1 * shf[1][1]);
            af[0][2] = packh2(e0 * shf[0][2], e0 * shf[0][3]);
            af[0][3] = packh2(e1 * shf[1][2], e1 * shf[1][3]);
            af[1][0] = packh2(e2 * shf[2][0], e2 * shf[2][1]);
            af[1][1] = packh2(e3 * shf[3][0], e3 * shf[3][1]);
            af[1][2] = packh2(e2 * shf[2][2], e2 * shf[2][3]);
            af[1][3] = packh2(e3 * shf[3][2], e3 * shf[3][3]);

            uint32_t bf[4][4];
#pragma unroll
            for (int np = 0; np < 4; np++)
                ldsm4(bf[np], sBp + (wn + np * 16 + b_r8 + l7) * 72 + ks * 16 + b_k8);
#pragma unroll
            for (int np = 0; np < 4; np++) {
                mma_f16(acc[0][2 * np],     af[0], &bf[np][0]);
                mma_f16(acc[0][2 * np + 1], af[0], &bf[np][2]);
                mma_f16(acc[1][2 * np],     af[1], &bf[np][0]);
                mma_f16(acc[1][2 * np + 1], af[1], &bf[np][2]);
            }
        }
        if (kc < 15) {
            CP_WAIT1();       // next stage complete (lookahead stage may still fly)
            __syncthreads();
        }
    }

    // epilogue: value = acc * radial (radial fp16, incl. bias)
#pragma unroll
    for (int mt = 0; mt < 2; mt++)
#pragma unroll
        for (int nt = 0; nt < 8; nt++) {
            int er = m0 + wm + mt * 16 + g;
            int cn = n0 + wn + nt * 8 + tg * 2;
            if (er < M) {
                float2 rr = __half22float2(*(const half2*)&g_radial[er * 512 + cn]);
                *(half2*)&g_value[er * 512 + cn] =
                    __floats2half2_rn(acc[mt][nt][0] * rr.x, acc[mt][nt][1] * rr.y);
            }
            if (er + 8 < M) {
                float2 rr = __half22float2(*(const half2*)&g_radial[(er + 8) * 512 + cn]);
                *(half2*)&g_value[(er + 8) * 512 + cn] =
                    __floats2half2_rn(acc[mt][nt][2] * rr.x, acc[mt][nt][3] * rr.y);
            }
        }
}

// ---------------- segment offsets (triple_idx0 sorted) ----------------
__global__ void k_seg(const int* __restrict__ t0, int E, int T) {
    int e = blockIdx.x * blockDim.x + threadIdx.x;
    if (e > E) return;
    int lo = 0, hi = T;
    while (lo < hi) {
        int mid = (lo + hi) >> 1;
        if (t0[mid] < e) lo = mid + 1; else hi = mid;
    }
    g_seg[e] = lo;
}

// ---------------- fused gather index: g_tidx[t] = inv[t1[t]] ----------------
__global__ void k_tidx(const int* __restrict__ t1, const int* __restrict__ inv, int T) {
    int t = blockIdx.x * blockDim.x + threadIdx.x;
    if (t < T) g_tidx[t] = inv[t1[t]];
}

// ---------------- alpha MLPs (fp32, thread-per-triplet) ----------------
__global__ __launch_bounds__(128) void k_alpha(
    const float* __restrict__ emb2, const float* __restrict__ emb3,
    const float* __restrict__ aW1, const float* __restrict__ ab1,
    const float* __restrict__ ag1, const float* __restrict__ abe1,
    const float* __restrict__ aW2, const float* __restrict__ ab2,
    const float* __restrict__ ag2, const float* __restrict__ abe2,
    const float* __restrict__ aW3, const float* __restrict__ ab3, int T) {
    __shared__ float sW[64 * 64];
    __shared__ float sW3[64 * 8];
    __shared__ float sP[6 * 64];
    __shared__ float sb3[8];
    __shared__ float sx[64 * 129];
    int tid = threadIdx.x;
    int base = blockIdx.x * 128;
    int tri = base + tid;
    bool act = tri < T;
    float res[8];

    for (int br = 0; br < 2; br++) {
        const float* emb = br ? emb3 : emb2;
        __syncthreads();
        for (int li = tid; li < 128 * 64; li += 128) {
            int r = li >> 6, c = li & 63;
            int tt = min(base + r, T - 1);
            sx[c * 129 + r] = emb[tt * 64 + c];
        }
        for (int li = tid; li < 4096; li += 128) sW[li] = aW1[br * 4096 + li];
        for (int li = tid; li < 512; li += 128) sW3[li] = aW3[br * 512 + li];
        if (tid < 64) {
            sP[tid] = ab1[br * 64 + tid];        sP[64 + tid] = ag1[br * 64 + tid];
            sP[128 + tid] = abe1[br * 64 + tid]; sP[192 + tid] = ab2[br * 64 + tid];
            sP[256 + tid] = ag2[br * 64 + tid];  sP[320 + tid] = abe2[br * 64 + tid];
        }
        if (tid < 8) sb3[tid] = ab3[br * 8 + tid];
        __syncthreads();

        const float4* sW4 = (const float4*)sW;
        float h[64];
        // layer 1
#pragma unroll
        for (int j = 0; j < 64; j++) h[j] = sP[j];
        for (int i = 0; i < 64; i++) {
            float xv = sx[i * 129 + tid];
#pragma unroll
            for (int j4 = 0; j4 < 16; j4++) {
                float4 w = sW4[i * 16 + j4];
                h[4 * j4]     = fmaf(xv, w.x, h[4 * j4]);
                h[4 * j4 + 1] = fmaf(xv, w.y, h[4 * j4 + 1]);
                h[4 * j4 + 2] = fmaf(xv, w.z, h[4 * j4 + 2]);
                h[4 * j4 + 3] = fmaf(xv, w.w, h[4 * j4 + 3]);
            }
        }
        {
            float mu = 0.f;
#pragma unroll
            for (int j = 0; j < 64; j++) mu += h[j];
            mu *= (1.f / 64.f);
            float v = 0.f;
#pragma unroll
            for (int j = 0; j < 64; j++) { float d = h[j] - mu; v = fmaf(d, d, v); }
            float rr = rsqrtf(v * (1.f / 64.f) + 1e-6f);
#pragma unroll
            for (int j = 0; j < 64; j++) {
                float y = (h[j] - mu) * rr * sP[64 + j] + sP[128 + j];
                sx[j * 129 + tid] = y / (1.f + __expf(-y));
            }
        }
        __syncthreads();
        for (int li = tid; li < 4096; li += 128) sW[li] = aW2[br * 4096 + li];
        __syncthreads();
        // layer 2
#pragma unroll
        for (int j = 0; j < 64; j++) h[j] = sP[192 + j];
        for (int i = 0; i < 64; i++) {
            float xv = sx[i * 129 + tid];
#pragma unroll
            for (int j4 = 0; j4 < 16; j4++) {
                float4 w = sW4[i * 16 + j4];
                h[4 * j4]     = fmaf(xv, w.x, h[4 * j4]);
                h[4 * j4 + 1] = fmaf(xv, w.y, h[4 * j4 + 1]);
                h[4 * j4 + 2] = fmaf(xv, w.z, h[4 * j4 + 2]);
                h[4 * j4 + 3] = fmaf(xv, w.w, h[4 * j4 + 3]);
            }
        }
        {
            float mu = 0.f;
#pragma unroll
            for (int j = 0; j < 64; j++) mu += h[j];
            mu *= (1.f / 64.f);
            float v = 0.f;
#pragma unroll
            for (int j = 0; j < 64; j++) { float d = h[j] - mu; v = fmaf(d, d, v); }
            float rr = rsqrtf(v * (1.f / 64.f) + 1e-6f);
#pragma unroll
            for (int j = 0; j < 64; j++) {
                float y = (h[j] - mu) * rr * sP[256 + j] + sP[320 + j];
                sx[j * 129 + tid] = y / (1.f + __expf(-y));
            }
        }
        // layer 3 (reads own column only)
        const float4* sW34 = (const float4*)sW3;
        float o[8];
#pragma unroll
        for (int j = 0; j < 8; j++) o[j] = sb3[j];
        for (int i = 0; i < 64; i++) {
            float xv = sx[i * 129 + tid];
            float4 w0 = sW34[i * 2], w1 = sW34[i * 2 + 1];
            o[0] = fmaf(xv, w0.x, o[0]); o[1] = fmaf(xv, w0.y, o[1]);
            o[2] = fmaf(xv, w0.z, o[2]); o[3] = fmaf(xv, w0.w, o[3]);
            o[4] = fmaf(xv, w1.x, o[4]); o[5] = fmaf(xv, w1.y, o[5]);
            o[6] = fmaf(xv, w1.z, o[6]); o[7] = fmaf(xv, w1.w, o[7]);
        }
#pragma unroll
        for (int j = 0; j < 8; j++) res[j] = br ? res[j] * o[j] : o[j];
    }
    if (act) {
        float4* ap = (float4*)(g_alpha + (size_t)tri * 8);
        ap[0] = make_float4(res[0], res[1], res[2], res[3]);
        ap[1] = make_float4(res[4], res[5], res[6], res[7]);
    }
}

// ---------------- segment softmax + gather-aggregate ----------------
__global__ void k_attn(int E) {
    int e = blockIdx.x * 8 + (threadIdx.x >> 5);
    if (e >= E) return;
    int lane = threadIdx.x & 31;
    int lo = g_seg[e], hi = g_seg[e + 1];
    int h = lane >> 2;
    float m = -1e30f;
    for (int t = lo; t < hi; t++) m = fmaxf(m, g_alpha[t * 8 + h]);
    float s = 0.f;
    for (int t = lo; t < hi; t++) s += __expf(g_alpha[t * 8 + h] - m);
    float inv_s = (s > 0.f) ? 1.f / s : 0.f;
    float acc[16];
#pragma unroll
    for (int j = 0; j < 16; j++) acc[j] = 0.f;
    for (int t = lo; t < hi; t++) {
        int es = g_tidx[t];
        float w = __expf(g_alpha[t * 8 + h] - m) * inv_s;
        const uint4* vp = (const uint4*)(g_value + (size_t)es * 512 + lane * 16);
        uint4 u0 = vp[0], u1 = vp[1];
        const half2* p0 = (const half2*)&u0;
        const half2* p1 = (const half2*)&u1;
#pragma unroll
        for (int j = 0; j < 4; j++) {
            float2 f0 = __half22float2(p0[j]);
            float2 f1 = __half22float2(p1[j]);
            acc[2 * j]         = fmaf(w, f0.x, acc[2 * j]);
            acc[2 * j + 1]     = fmaf(w, f0.y, acc[2 * j + 1]);
            acc[8 + 2 * j]     = fmaf(w, f1.x, acc[8 + 2 * j]);
            acc[8 + 2 * j + 1] = fmaf(w, f1.y, acc[8 + 2 * j + 1]);
        }
    }
    half2 o[8];
#pragma unroll
    for (int j = 0; j < 8; j++) o[j] = __floats2half2_rn(acc[2 * j], acc[2 * j + 1]);
    uint4* fp = (uint4*)(g_fea + (size_t)e * 512 + lane * 16);
    fp[0] = *(uint4*)&o[0];
    fp[1] = *(uint4*)&o[4];
}

// ---------------- out = fea @ lin_W + lin_b  (pipelined) ----------------
__global__ __launch_bounds__(256, 2) void k_out(const float* __restrict__ linb,
                                                float* __restrict__ out, int M) {
    __shared__ half sA[2][128 * 72];
    __shared__ half sB[2][128 * 72];
    int m0 = blockIdx.x * 128;
    int tid = threadIdx.x, lane = tid & 31, wid = tid >> 5;
    int wm = (wid & 3) * 32, wn = (wid >> 2) * 64;
    int g = lane >> 2, tg = lane & 3;
    int row = tid >> 1, koff = (tid & 1) * 32;
    int erow = min(m0 + row, M - 1);

    float acc[2][8][4];
#pragma unroll
    for (int a = 0; a < 2; a++)
#pragma unroll
        for (int b = 0; b < 8; b++)
#pragma unroll
            for (int c = 0; c < 4; c++) acc[a][b][c] = 0.f;

    {
        const half* srcA = g_fea + (size_t)erow * 512 + koff;
        const half* srcB = g_linWT + row * 512 + koff;
#pragma unroll
        for (int j = 0; j < 4; j++) {
            cp16(&sA[0][row * 72 + koff + j * 8], srcA + j * 8);
            cp16(&sB[0][row * 72 + koff + j * 8], srcB + j * 8);
        }
        CP_COMMIT(); CP_WAIT0();
        __syncthreads();
    }

    for (int kc = 0; kc < 8; kc++) {
        int p = kc & 1;
        if (kc < 7) {
            const half* srcA = g_fea + (size_t)erow * 512 + (kc + 1) * 64 + koff;
            const half* srcB = g_linWT + row * 512 + (kc + 1) * 64 + koff;
#pragma unroll
            for (int j = 0; j < 4; j++) {
                cp16(&sA[1 - p][row * 72 + koff + j * 8], srcA + j * 8);
                cp16(&sB[1 - p][row * 72 + koff + j * 8], srcB + j * 8);
            }
            CP_COMMIT();
        }
        tile_mma(sA[p], sB[p], wm, wn, lane, acc);
        if (kc < 7) { CP_WAIT0(); __syncthreads(); }
    }
#pragma unroll
    for (int mt = 0; mt < 2; mt++)
#pragma unroll
        for (int nt = 0; nt < 8; nt++) {
            int er = m0 + wm + mt * 16 + g;
            int cn = wn + nt * 8 + tg * 2;
            float bb0 = linb[cn], bb1 = linb[cn + 1];
            if (er < M)
                *(float2*)&out[(size_t)er * 128 + cn] =
                    make_float2(acc[mt][nt][0] + bb0, acc[mt][nt][1] + bb1);
            if (er + 8 < M)
                *(float2*)&out[(size_t)(er + 8) * 128 + cn] =
                    make_float2(acc[mt][nt][2] + bb0, acc[mt][nt][3] + bb1);
        }
}

// ---------------- launcher ----------------
// Two independent chains overlapped on streams (graph capture preserves the fork):
//   legacy stream: k_prep -> k_hidden -> k_radial -> k_value -> [join] -> k_attn -> k_out
//   side stream  : k_seg, k_tidx, k_alpha   (pure fp32-FMA; fills SMs as k_value CTAs drain)
extern "C" void kernel_launch(void* const* d_in, const int* in_sizes, int n_in,
                              void* d_out, int out_size) {
    const float* edge_in = (const float*)d_in[0];
    const int*   inv     = (const int*)d_in[1];
    const float* esh     = (const float*)d_in[2];
    const float* elen    = (const float*)d_in[3];
    const int*   t0      = (const int*)d_in[6];
    const int*   t1      = (const int*)d_in[7];
    const float* emb2    = (const float*)d_in[8];
    const float* emb3    = (const float*)d_in[9];
    const float* Wtp     = (const float*)d_in[11];
    const float* rW1     = (const float*)d_in[12];
    const float* rb1     = (const float*)d_in[13];
    const float* rW2     = (const float*)d_in[14];
    const float* rb2     = (const float*)d_in[15];
    const float* aW1     = (const float*)d_in[16];
    const float* ab1     = (const float*)d_in[17];
    const float* ag1     = (const float*)d_in[18];
    const float* abe1    = (const float*)d_in[19];
    const float* aW2     = (const float*)d_in[20];
    const float* ab2     = (const float*)d_in[21];
    const float* ag2     = (const float*)d_in[22];
    const float* abe2    = (const float*)d_in[23];
    const float* aW3     = (const float*)d_in[24];
    const float* ab3     = (const float*)d_in[25];
    const float* linW    = (const float*)d_in[26];
    const float* linb    = (const float*)d_in[27];
    int E = in_sizes[0] / 64;
    int T = in_sizes[6];

    // Created once on the first (correctness, non-capture) call; only
    // record/wait/launch happen during capture. No device memory involved.
    static cudaStream_t s1 = nullptr;
    static cudaEvent_t evFork = nullptr, evJoin = nullptr;
    if (!s1) {
        cudaStreamCreateWithFlags(&s1, cudaStreamNonBlocking);
        cudaEventCreateWithFlags(&evFork, cudaEventDisableTiming);
        cudaEventCreateWithFlags(&evJoin, cudaEventDisableTiming);
    }

    // fork side chain
    cudaEventRecord(evFork, 0);
    cudaStreamWaitEvent(s1, evFork, 0);
    k_seg<<<CDIV(E + 1, 256), 256, 0, s1>>>(t0, E, T);
    k_tidx<<<CDIV(T, 256), 256, 0, s1>>>(t1, inv, T);
    k_alpha<<<CDIV(T, 128), 128, 0, s1>>>(emb2, emb3, aW1, ab1, ag1, abe1,
                                          aW2, ab2, ag2, abe2, aW3, ab3, T);
    cudaEventRecord(evJoin, s1);

    // main chain
    k_prep<<<512, 256>>>(Wtp, rW2, linW);
    k_hidden<<<CDIV(E, 4), 256>>>(elen, rW1, rb1, E);
    k_radial<<<dim3(CDIV(E, 128), 4), 256>>>(rb2, E);
    k_value<<<dim3(CDIV(E, 128), 4), 256>>>(edge_in, esh, E);

    // join, then tail
    cudaStreamWaitEvent(0, evJoin, 0);
    k_attn<<<CDIV(E, 8), 256>>>(E);
    k_out<<<CDIV(E, 128), 256>>>(linb, (float*)d_out, E);
}

// round 16
// speedup vs baseline: 1.0654x; 1.0138x over previous
#include <cuda_runtime.h>
#include <cuda_fp16.h>
#include <cstdint>

#define CDIV(a,b) (((a)+(b)-1)/(b))

// ---------------- static device scratch ----------------
__device__ __align__(16) half  g_WtpT  [512 * 1024];
__device__ __align__(16) half  g_W2T   [512 * 64];
__device__ __align__(16) half  g_linWT [128 * 512];
__device__ __align__(16) float g_hidden[160000 * 64];
__device__ __align__(16) half  g_radial[160000 * 512];
__device__ __align__(16) half  g_value [160000 * 512];
__device__ __align__(16) float g_alpha [250000 * 8];
__device__              int    g_seg   [160001];
__device__              int    g_tidx  [250000];
__device__ __align__(16) half  g_fea   [160000 * 512];

// ---------------- PTX helpers ----------------
__device__ __forceinline__ void mma_f16(float* c, const uint32_t* a, const uint32_t* b) {
    asm volatile(
        "mma.sync.aligned.m16n8k16.row.col.f32.f16.f16.f32 "
        "{%0,%1,%2,%3},{%4,%5,%6,%7},{%8,%9},{%0,%1,%2,%3};\n"
        : "+f"(c[0]), "+f"(c[1]), "+f"(c[2]), "+f"(c[3])
        : "r"(a[0]), "r"(a[1]), "r"(a[2]), "r"(a[3]), "r"(b[0]), "r"(b[1]));
}

__device__ __forceinline__ void ldsm4(uint32_t* d, const half* p) {
    uint32_t a = (uint32_t)__cvta_generic_to_shared(p);
    asm volatile("ldmatrix.sync.aligned.m8n8.x4.shared.b16 {%0,%1,%2,%3},[%4];\n"
        : "=r"(d[0]), "=r"(d[1]), "=r"(d[2]), "=r"(d[3]) : "r"(a));
}

__device__ __forceinline__ void cp16(void* smem, const void* gmem) {
    uint32_t s = (uint32_t)__cvta_generic_to_shared(smem);
    asm volatile("cp.async.cg.shared.global [%0], [%1], 16;\n" :: "r"(s), "l"(gmem));
}
#define CP_COMMIT() asm volatile("cp.async.commit_group;\n")
#define CP_WAIT0()  asm volatile("cp.async.wait_group 0;\n")
#define CP_WAIT1()  asm volatile("cp.async.wait_group 1;\n")

__device__ __forceinline__ uint32_t packh2(float a, float b) {
    half2 h = __floats2half2_rn(a, b);
    return *(uint32_t*)&h;
}

// one 64-deep K-chunk of mma on 128x128 tile; warp covers 32(m)x64(n).
// smem row stride = 72 halfs (144B): ldmatrix row addrs hit 32 distinct banks.
// (used by k_radial / k_out)
__device__ __forceinline__ void tile_mma(const half* sA, const half* sB,
                                         int wm, int wn, int lane,
                                         float acc[2][8][4]) {
    int r15 = lane & 15;
    int a_k8 = ((lane >> 4) & 1) * 8;
    int b_r8 = ((lane >> 4) & 1) * 8;
    int b_k8 = lane & 8;
    int l7 = lane & 7;
#pragma unroll
    for (int ks = 0; ks < 4; ks++) {
        uint32_t af[2][4];
#pragma unroll
        for (int mt = 0; mt < 2; mt++)
            ldsm4(af[mt], sA + (wm + mt * 16 + r15) * 72 + ks * 16 + a_k8);
        uint32_t bf[4][4];
#pragma unroll
        for (int np = 0; np < 4; np++)
            ldsm4(bf[np], sB + (wn + np * 16 + b_r8 + l7) * 72 + ks * 16 + b_k8);
#pragma unroll
        for (int np = 0; np < 4; np++) {
            mma_f16(acc[0][2 * np],     af[0], &bf[np][0]);
            mma_f16(acc[0][2 * np + 1], af[0], &bf[np][2]);
            mma_f16(acc[1][2 * np],     af[1], &bf[np][0]);
            mma_f16(acc[1][2 * np + 1], af[1], &bf[np][2]);
        }
    }
}

// ---------------- weight prep ----------------
__global__ void k_prep(const float* __restrict__ Wtp, const float* __restrict__ W2,
                       const float* __restrict__ linW) {
    int i = blockIdx.x * blockDim.x + threadIdx.x;
    int stride = gridDim.x * blockDim.x;
    for (int idx = i; idx < 512 * 1024; idx += stride) {
        int n = idx >> 10, k = idx & 1023;
        g_WtpT[idx] = __float2half_rn(Wtp[k * 512 + n]);
    }
    for (int idx = i; idx < 512 * 64; idx += stride) {
        int n = idx >> 6, k = idx & 63;
        g_W2T[idx] = __float2half_rn(W2[k * 512 + n]);
    }
    for (int idx = i; idx < 128 * 512; idx += stride) {
        int n = idx >> 9, k = idx & 511;
        g_linWT[idx] = __float2half_rn(linW[k * 128 + n]);
    }
}

// ---------------- hidden = silu(emb @ W1 + b1) ----------------
__global__ void k_hidden(const float* __restrict__ emb, const float* __restrict__ W1,
                         const float* __restrict__ b1, int E) {
    __shared__ float s_e[4][64];
    int tid = threadIdx.x;
    int slot = tid >> 6, j = tid & 63;
    int e = blockIdx.x * 4 + slot;
    int ec = min(e, E - 1);
    s_e[slot][j] = emb[ec * 64 + j];
    __syncthreads();
    float acc = b1[j];
#pragma unroll 8
    for (int i = 0; i < 64; i++) acc = fmaf(s_e[slot][i], W1[i * 64 + j], acc);
    float y = acc / (1.f + __expf(-acc));
    if (e < E) g_hidden[e * 64 + j] = y;
}

// ---------------- radial = hidden @ W2 + b2  (K=64 mma) ----------------
__global__ __launch_bounds__(256) void k_radial(const float* __restrict__ b2, int M) {
    __shared__ half sA[128 * 72];
    __shared__ half sB[128 * 72];
    int m0 = blockIdx.x * 128, n0 = blockIdx.y * 128;
    int tid = threadIdx.x, lane = tid & 31, wid = tid >> 5;
    int wm = (wid & 3) * 32, wn = (wid >> 2) * 64;
    int g = lane >> 2, tg = lane & 3;
    int row = tid >> 1, koff = (tid & 1) * 32;
    int erow = min(m0 + row, M - 1);

    float acc[2][8][4];
#pragma unroll
    for (int a = 0; a < 2; a++)
#pragma unroll
        for (int b = 0; b < 8; b++)
#pragma unroll
            for (int c = 0; c < 4; c++) acc[a][b][c] = 0.f;

    const float4* hp = (const float4*)(g_hidden + erow * 64 + koff);
#pragma unroll
    for (int j = 0; j < 8; j++) {
        float4 v = hp[j];
        *(half2*)&sA[row * 72 + koff + j * 4]     = __floats2half2_rn(v.x, v.y);
        *(half2*)&sA[row * 72 + koff + j * 4 + 2] = __floats2half2_rn(v.z, v.w);
    }
    {
        const uint4* s = (const uint4*)(g_W2T + (n0 + row) * 64 + koff);
        uint4* d = (uint4*)&sB[row * 72 + koff];
        d[0] = s[0]; d[1] = s[1]; d[2] = s[2]; d[3] = s[3];
    }
    __syncthreads();
    tile_mma(sA, sB, wm, wn, lane, acc);

#pragma unroll
    for (int mt = 0; mt < 2; mt++)
#pragma unroll
        for (int nt = 0; nt < 8; nt++) {
            int er = m0 + wm + mt * 16 + g;
            int cn = n0 + wn + nt * 8 + tg * 2;
            float bb0 = b2[cn], bb1 = b2[cn + 1];
            if (er < M)
                *(half2*)&g_radial[er * 512 + cn] =
                    __floats2half2_rn(acc[mt][nt][0] + bb0, acc[mt][nt][1] + bb1);
            if (er + 8 < M)
                *(half2*)&g_radial[(er + 8) * 512 + cn] =
                    __floats2half2_rn(acc[mt][nt][2] + bb0, acc[mt][nt][3] + bb1);
        }
}

// ---------------- value = (z @ W_tp) * radial ----------------
// 512 threads, CTA tile 128(m) x 64(n), warp tile 16m x 32n (16 warps: 8m x 2n).
// K=1024, register-built A, 3-stage cp.async ring. Small accumulator (16 regs)
// => 63-reg cap => 2 CTAs/SM = 32 warps/SM for latency hiding.
__global__ __launch_bounds__(512, 2) void k_value(const float* __restrict__ ein,
                                                  const float* __restrict__ esh, int M) {
    __shared__ half  sB[3][64 * 72];
    __shared__ float sE[3][128 * 4];
    int m0 = blockIdx.x * 128, n0 = blockIdx.y * 64;
    int tid = threadIdx.x, lane = tid & 31, wid = tid >> 5;
    int wm = (wid & 7) * 16, wn = (wid >> 3) * 32;
    int g = lane >> 2, tg = lane & 3;
    int brow = tid >> 3, bseg = tid & 7;     // B loader: 64 rows x 8 segs of 8 halfs

    int b_r8 = ((lane >> 4) & 1) * 8;
    int b_k8 = lane & 8;
    int l7 = lane & 7;

    // A-fragment rows owned by this thread (2 row-halves of one m16 tile)
    int lr0 = wm + g, lr1 = wm + g + 8;
    int r0 = min(m0 + lr0, M - 1), r1 = min(m0 + lr1, M - 1);

    // SH columns owned by this thread (fixed across all K)
    float shf[2][4];
    {
        const float* sp0 = esh + (size_t)r0 * 16;
        const float* sp1 = esh + (size_t)r1 * 16;
        shf[0][0] = __ldg(&sp0[tg * 2]);     shf[0][1] = __ldg(&sp0[tg * 2 + 1]);
        shf[0][2] = __ldg(&sp0[tg * 2 + 8]); shf[0][3] = __ldg(&sp0[tg * 2 + 9]);
        shf[1][0] = __ldg(&sp1[tg * 2]);     shf[1][1] = __ldg(&sp1[tg * 2 + 1]);
        shf[1][2] = __ldg(&sp1[tg * 2 + 8]); shf[1][3] = __ldg(&sp1[tg * 2 + 9]);
    }

    // stage loaders
    int e_row = min(m0 + (tid & 127), M - 1);   // threads 0..127 load ein rows
    auto load_stage = [&](int s, int kc) {
        cp16(&sB[s][brow * 72 + bseg * 8],
             g_WtpT + (size_t)(n0 + brow) * 1024 + kc * 64 + bseg * 8);
        if (tid < 128)
            cp16(&sE[s][tid * 4], ein + (size_t)e_row * 64 + kc * 4);
    };

    float acc[4][4];
#pragma unroll
    for (int a = 0; a < 4; a++)
#pragma unroll
        for (int c = 0; c < 4; c++) acc[a][c] = 0.f;

    // prologue: stage chunks 0 and 1
    load_stage(0, 0); CP_COMMIT();
    load_stage(1, 1); CP_COMMIT();
    CP_WAIT1();               // stage 0 complete
    __syncthreads();

    for (int kc = 0; kc < 16; kc++) {
        int p = kc % 3;
        if (kc < 14) { load_stage((kc + 2) % 3, kc + 2); CP_COMMIT(); }

        float4 ev0 = *(const float4*)&sE[p][lr0 * 4];
        float4 ev1 = *(const float4*)&sE[p][lr1 * 4];

        const half* sBp = sB[p];
#pragma unroll
        for (int ks = 0; ks < 4; ks++) {
            float e0 = ((const float*)&ev0)[ks];
            float e1 = ((const float*)&ev1)[ks];
            uint32_t af[4];
            af[0] = packh2(e0 * shf[0][0], e0 * shf[0][1]);
            af[1] = packh2(e1 * shf[1][0], e1 * shf[1][1]);
            af[2] = packh2(e0 * shf[0][2], e0 * shf[0][3]);
            af[3] = packh2(e1 * shf[1][2], e1 * shf[1][3]);

            uint32_t bf[2][4];
#pragma unroll
            for (int np = 0; np < 2; np++)
                ldsm4(bf[np], sBp + (wn + np * 16 + b_r8 + l7) * 72 + ks * 16 + b_k8);
            mma_f16(acc[0], af, &bf[0][0]);
            mma_f16(acc[1], af, &bf[0][2]);
            mma_f16(acc[2], af, &bf[1][0]);
            mma_f16(acc[3], af, &bf[1][2]);
        }
        if (kc < 15) {
            CP_WAIT1();       // next stage complete (lookahead stage may still fly)
            __syncthreads();
        }
    }

    // epilogue: value = acc * radial (radial fp16, incl. bias)
    int er0 = m0 + wm + g;
    int er1 = er0 + 8;
#pragma unroll
    for (int nt = 0; nt < 4; nt++) {
        int cn = n0 + wn + nt * 8 + tg * 2;
        if (er0 < M) {
            float2 rr = __half22float2(*(const half2*)&g_radial[(size_t)er0 * 512 + cn]);
            *(half2*)&g_value[(size_t)er0 * 512 + cn] =
                __floats2half2_rn(acc[nt][0] * rr.x, acc[nt][1] * rr.y);
        }
        if (er1 < M) {
            float2 rr = __half22float2(*(const half2*)&g_radial[(size_t)er1 * 512 + cn]);
            *(half2*)&g_value[(size_t)er1 * 512 + cn] =
                __floats2half2_rn(acc[nt][2] * rr.x, acc[nt][3] * rr.y);
        }
    }
}

// ---------------- segment offsets (triple_idx0 sorted) ----------------
__global__ void k_seg(const int* __restrict__ t0, int E, int T) {
    int e = blockIdx.x * blockDim.x + threadIdx.x;
    if (e > E) return;
    int lo = 0, hi = T;
    while (lo < hi) {
        int mid = (lo + hi) >> 1;
        if (t0[mid] < e) lo = mid + 1; else hi = mid;
    }
    g_seg[e] = lo;
}

// ---------------- fused gather index: g_tidx[t] = inv[t1[t]] ----------------
__global__ void k_tidx(const int* __restrict__ t1, const int* __restrict__ inv, int T) {
    int t = blockIdx.x * blockDim.x + threadIdx.x;
    if (t < T) g_tidx[t] = inv[t1[t]];
}

// ---------------- alpha MLPs (fp32, thread-per-triplet) ----------------
__global__ __launch_bounds__(128) void k_alpha(
    const float* __restrict__ emb2, const float* __restrict__ emb3,
    const float* __restrict__ aW1, const float* __restrict__ ab1,
    const float* __restrict__ ag1, const float* __restrict__ abe1,
    const float* __restrict__ aW2, const float* __restrict__ ab2,
    const float* __restrict__ ag2, const float* __restrict__ abe2,
    const float* __restrict__ aW3, const float* __restrict__ ab3, int T) {
    __shared__ float sW[64 * 64];
    __shared__ float sW3[64 * 8];
    __shared__ float sP[6 * 64];
    __shared__ float sb3[8];
    __shared__ float sx[64 * 129];
    int tid = threadIdx.x;
    int base = blockIdx.x * 128;
    int tri = base + tid;
    bool act = tri < T;
    float res[8];

    for (int br = 0; br < 2; br++) {
        const float* emb = br ? emb3 : emb2;
        __syncthreads();
        for (int li = tid; li < 128 * 64; li += 128) {
            int r = li >> 6, c = li & 63;
            int tt = min(base + r, T - 1);
            sx[c * 129 + r] = emb[tt * 64 + c];
        }
        for (int li = tid; li < 4096; li += 128) sW[li] = aW1[br * 4096 + li];
        for (int li = tid; li < 512; li += 128) sW3[li] = aW3[br * 512 + li];
        if (tid < 64) {
            sP[tid] = ab1[br * 64 + tid];        sP[64 + tid] = ag1[br * 64 + tid];
            sP[128 + tid] = abe1[br * 64 + tid]; sP[192 + tid] = ab2[br * 64 + tid];
            sP[256 + tid] = ag2[br * 64 + tid];  sP[320 + tid] = abe2[br * 64 + tid];
        }
        if (tid < 8) sb3[tid] = ab3[br * 8 + tid];
        __syncthreads();

        const float4* sW4 = (const float4*)sW;
        float h[64];
        // layer 1
#pragma unroll
        for (int j = 0; j < 64; j++) h[j] = sP[j];
        for (int i = 0; i < 64; i++) {
            float xv = sx[i * 129 + tid];
#pragma unroll
            for (int j4 = 0; j4 < 16; j4++) {
                float4 w = sW4[i * 16 + j4];
                h[4 * j4]     = fmaf(xv, w.x, h[4 * j4]);
                h[4 * j4 + 1] = fmaf(xv, w.y, h[4 * j4 + 1]);
                h[4 * j4 + 2] = fmaf(xv, w.z, h[4 * j4 + 2]);
                h[4 * j4 + 3] = fmaf(xv, w.w, h[4 * j4 + 3]);
            }
        }
        {
            float mu = 0.f;
#pragma unroll
            for (int j = 0; j < 64; j++) mu += h[j];
            mu *= (1.f / 64.f);
            float v = 0.f;
#pragma unroll
            for (int j = 0; j < 64; j++) { float d = h[j] - mu; v = fmaf(d, d, v); }
            float rr = rsqrtf(v * (1.f / 64.f) + 1e-6f);
#pragma unroll
            for (int j = 0; j < 64; j++) {
                float y = (h[j] - mu) * rr * sP[64 + j] + sP[128 + j];
                sx[j * 129 + tid] = y / (1.f + __expf(-y));
            }
        }
        __syncthreads();
        for (int li = tid; li < 4096; li += 128) sW[li] = aW2[br * 4096 + li];
        __syncthreads();
        // layer 2
#pragma unroll
        for (int j = 0; j < 64; j++) h[j] = sP[192 + j];
        for (int i = 0; i < 64; i++) {
            float xv = sx[i * 129 + tid];
#pragma unroll
            for (int j4 = 0; j4 < 16; j4++) {
                float4 w = sW4[i * 16 + j4];
                h[4 * j4]     = fmaf(xv, w.x, h[4 * j4]);
                h[4 * j4 + 1] = fmaf(xv, w.y, h[4 * j4 + 1]);
                h[4 * j4 + 2] = fmaf(xv, w.z, h[4 * j4 + 2]);
                h[4 * j4 + 3] = fmaf(xv, w.w, h[4 * j4 + 3]);
            }
        }
        {
            float mu = 0.f;
#pragma unroll
            for (int j = 0; j < 64; j++) mu += h[j];
            mu *= (1.f / 64.f);
            float v = 0.f;
#pragma unroll
            for (int j = 0; j < 64; j++) { float d = h[j] - mu; v = fmaf(d, d, v); }
            float rr = rsqrtf(v * (1.f / 64.f) + 1e-6f);
#pragma unroll
            for (int j = 0; j < 64; j++) {
                float y = (h[j] - mu) * rr * sP[256 + j] + sP[320 + j];
                sx[j * 129 + tid] = y / (1.f + __expf(-y));
            }
        }
        // layer 3 (reads own column only)
        const float4* sW34 = (const float4*)sW3;
        float o[8];
#pragma unroll
        for (int j = 0; j < 8; j++) o[j] = sb3[j];
        for (int i = 0; i < 64; i++) {
            float xv = sx[i * 129 + tid];
            float4 w0 = sW34[i * 2], w1 = sW34[i * 2 + 1];
            o[0] = fmaf(xv, w0.x, o[0]); o[1] = fmaf(xv, w0.y, o[1]);
            o[2] = fmaf(xv, w0.z, o[2]); o[3] = fmaf(xv, w0.w, o[3]);
            o[4] = fmaf(xv, w1.x, o[4]); o[5] = fmaf(xv, w1.y, o[5]);
            o[6] = fmaf(xv, w1.z, o[6]); o[7] = fmaf(xv, w1.w, o[7]);
        }
#pragma unroll
        for (int j = 0; j < 8; j++) res[j] = br ? res[j] * o[j] : o[j];
    }
    if (act) {
        float4* ap = (float4*)(g_alpha + (size_t)tri * 8);
        ap[0] = make_float4(res[0], res[1], res[2], res[3]);
        ap[1] = make_float4(res[4], res[5], res[6], res[7]);
    }
}

// ---------------- segment softmax + gather-aggregate ----------------
__global__ void k_attn(int E) {
    int e = blockIdx.x * 8 + (threadIdx.x >> 5);
    if (e >= E) return;
    int lane = threadIdx.x & 31;
    int lo = g_seg[e], hi = g_seg[e + 1];
    int h = lane >> 2;
    float m = -1e30f;
    for (int t = lo; t < hi; t++) m = fmaxf(m, g_alpha[t * 8 + h]);
    float s = 0.f;
    for (int t = lo; t < hi; t++) s += __expf(g_alpha[t * 8 + h] - m);
    float inv_s = (s > 0.f) ? 1.f / s : 0.f;
    float acc[16];
#pragma unroll
    for (int j = 0; j < 16; j++) acc[j] = 0.f;
    for (int t = lo; t < hi; t++) {
        int es = g_tidx[t];
        float w = __expf(g_alpha[t * 8 + h] - m) * inv_s;
        const uint4* vp = (const uint4*)(g_value + (size_t)es * 512 + lane * 16);
        uint4 u0 = vp[0], u1 = vp[1];
        const half2* p0 = (const half2*)&u0;
        const half2* p1 = (const half2*)&u1;
#pragma unroll
        for (int j = 0; j < 4; j++) {
            float2 f0 = __half22float2(p0[j]);
            float2 f1 = __half22float2(p1[j]);
            acc[2 * j]         = fmaf(w, f0.x, acc[2 * j]);
            acc[2 * j + 1]     = fmaf(w, f0.y, acc[2 * j + 1]);
            acc[8 + 2 * j]     = fmaf(w, f1.x, acc[8 + 2 * j]);
            acc[8 + 2 * j + 1] = fmaf(w, f1.y, acc[8 + 2 * j + 1]);
        }
    }
    half2 o[8];
#pragma unroll
    for (int j = 0; j < 8; j++) o[j] = __floats2half2_rn(acc[2 * j], acc[2 * j + 1]);
    uint4* fp = (uint4*)(g_fea + (size_t)e * 512 + lane * 16);
    fp[0] = *(uint4*)&o[0];
    fp[1] = *(uint4*)&o[4];
}

// ---------------- out = fea @ lin_W + lin_b  (pipelined) ----------------
__global__ __launch_bounds__(256, 2) void k_out(const float* __restrict__ linb,
                                                float* __restrict__ out, int M) {
    __shared__ half sA[2][128 * 72];
    __shared__ half sB[2][128 * 72];
    int m0 = blockIdx.x * 128;
    int tid = threadIdx.x, lane = tid & 31, wid = tid >> 5;
    int wm = (wid & 3) * 32, wn = (wid >> 2) * 64;
    int g = lane >> 2, tg = lane & 3;
    int row = tid >> 1, koff = (tid & 1) * 32;
    int erow = min(m0 + row, M - 1);

    float acc[2][8][4];
#pragma unroll
    for (int a = 0; a < 2; a++)
#pragma unroll
        for (int b = 0; b < 8; b++)
#pragma unroll
            for (int c = 0; c < 4; c++) acc[a][b][c] = 0.f;

    {
        const half* srcA = g_fea + (size_t)erow * 512 + koff;
        const half* srcB = g_linWT + row * 512 + koff;
#pragma unroll
        for (int j = 0; j < 4; j++) {
            cp16(&sA[0][row * 72 + koff + j * 8], srcA + j * 8);
            cp16(&sB[0][row * 72 + koff + j * 8], srcB + j * 8);
        }
        CP_COMMIT(); CP_WAIT0();
        __syncthreads();
    }

    for (int kc = 0; kc < 8; kc++) {
        int p = kc & 1;
        if (kc < 7) {
            const half* srcA = g_fea + (size_t)erow * 512 + (kc + 1) * 64 + koff;
            const half* srcB = g_linWT + row * 512 + (kc + 1) * 64 + koff;
#pragma unroll
            for (int j = 0; j < 4; j++) {
                cp16(&sA[1 - p][row * 72 + koff + j * 8], srcA + j * 8);
                cp16(&sB[1 - p][row * 72 + koff + j * 8], srcB + j * 8);
            }
            CP_COMMIT();
        }
        tile_mma(sA[p], sB[p], wm, wn, lane, acc);
        if (kc < 7) { CP_WAIT0(); __syncthreads(); }
    }
#pragma unroll
    for (int mt = 0; mt < 2; mt++)
#pragma unroll
        for (int nt = 0; nt < 8; nt++) {
            int er = m0 + wm + mt * 16 + g;
            int cn = wn + nt * 8 + tg * 2;
            float bb0 = linb[cn], bb1 = linb[cn + 1];
            if (er < M)
                *(float2*)&out[(size_t)er * 128 + cn] =
                    make_float2(acc[mt][nt][0] + bb0, acc[mt][nt][1] + bb1);
            if (er + 8 < M)
                *(float2*)&out[(size_t)(er + 8) * 128 + cn] =
                    make_float2(acc[mt][nt][2] + bb0, acc[mt][nt][3] + bb1);
        }
}

// ---------------- launcher ----------------
// Two independent chains overlapped on streams (graph capture preserves the fork):
//   legacy stream: k_prep -> k_hidden -> k_radial -> k_value -> [join] -> k_attn -> k_out
//   side stream  : k_seg, k_tidx, k_alpha
extern "C" void kernel_launch(void* const* d_in, const int* in_sizes, int n_in,
                              void* d_out, int out_size) {
    const float* edge_in = (const float*)d_in[0];
    const int*   inv     = (const int*)d_in[1];
    const float* esh     = (const float*)d_in[2];
    const float* elen    = (const float*)d_in[3];
    const int*   t0      = (const int*)d_in[6];
    const int*   t1      = (const int*)d_in[7];
    const float* emb2    = (const float*)d_in[8];
    const float* emb3    = (const float*)d_in[9];
    const float* Wtp     = (const float*)d_in[11];
    const float* rW1     = (const float*)d_in[12];
    const float* rb1     = (const float*)d_in[13];
    const float* rW2     = (const float*)d_in[14];
    const float* rb2     = (const float*)d_in[15];
    const float* aW1     = (const float*)d_in[16];
    const float* ab1     = (const float*)d_in[17];
    const float* ag1     = (const float*)d_in[18];
    const float* abe1    = (const float*)d_in[19];
    const float* aW2     = (const float*)d_in[20];
    const float* ab2     = (const float*)d_in[21];
    const float* ag2     = (const float*)d_in[22];
    const float* abe2    = (const float*)d_in[23];
    const float* aW3     = (const float*)d_in[24];
    const float* ab3     = (const float*)d_in[25];
    const float* linW    = (const float*)d_in[26];
    const float* linb    = (const float*)d_in[27];
    int E = in_sizes[0] / 64;
    int T = in_sizes[6];

    static cudaStream_t s1 = nullptr;
    static cudaEvent_t evFork = nullptr, evJoin = nullptr;
    if (!s1) {
        cudaStreamCreateWithFlags(&s1, cudaStreamNonBlocking);
        cudaEventCreateWithFlags(&evFork, cudaEventDisableTiming);
        cudaEventCreateWithFlags(&evJoin, cudaEventDisableTiming);
    }

    // fork side chain
    cudaEventRecord(evFork, 0);
    cudaStreamWaitEvent(s1, evFork, 0);
    k_seg<<<CDIV(E + 1, 256), 256, 0, s1>>>(t0, E, T);
    k_tidx<<<CDIV(T, 256), 256, 0, s1>>>(t1, inv, T);
    k_alpha<<<CDIV(T, 128), 128, 0, s1>>>(emb2, emb3, aW1, ab1, ag1, abe1,
                                          aW2, ab2, ag2, abe2, aW3, ab3, T);
    cudaEventRecord(evJoin, s1);

    // main chain
    k_prep<<<512, 256>>>(Wtp, rW2, linW);
    k_hidden<<<CDIV(E, 4), 256>>>(elen, rW1, rb1, E);
    k_radial<<<dim3(CDIV(E, 128), 4), 256>>>(rb2, E);
    k_value<<<dim3(CDIV(E, 128), 8), 512>>>(edge_in, esh, E);

    // join, then tail
    cudaStreamWaitEvent(0, evJoin, 0);
    k_attn<<<CDIV(E, 8), 256>>>(E);
    k_out<<<CDIV(E, 128), 256>>>(linb, (float*)d_out, E);
}